// round 3
// baseline (speedup 1.0000x reference)
#include <cuda_runtime.h>
#include <cstdint>

#define NPTS 16384
#define BATCH 16
#define INC 7

typedef unsigned long long u64;

__device__ __forceinline__ u64 fma2(u64 a, u64 b, u64 c) {
    u64 d; asm("fma.rn.f32x2 %0, %1, %2, %3;" : "=l"(d) : "l"(a), "l"(b), "l"(c)); return d;
}
__device__ __forceinline__ u64 pack2(float x, float y) {
    u64 r; asm("mov.b64 %0, {%1, %2};" : "=l"(r) : "f"(x), "f"(y)); return r;
}
__device__ __forceinline__ float2 unpack2(u64 p) {
    float2 v; asm("mov.b64 {%0, %1}, %2;" : "=f"(v.x), "=f"(v.y) : "l"(p)); return v;
}

// ---------------- scratch ----------------
__device__ float              g_h4[(size_t)BATCH * 128 * NPTS]; // (b, c, i)
__device__ unsigned char      g_gid[BATCH * NPTS];
__device__ unsigned long long g_pmax[BATCH * 1024];  // (valbits<<32)|(~idx)
__device__ unsigned int       g_gmax[4 * 1024];
__device__ float              g_u1[17 * 512];

// ---------------- kernel A: fused 7->64->64->64->128, register-resident ----------------
// smem = weights only:
//  w0:0(448) b0:448(64) w1:512(4096) b1:4608(64) w2:4672(4096) b2:8768(64)
//  w3:8832(8192) b3:17024(128)
#define KA_SMEM_FLOATS 17152

__device__ __forceinline__ void smcpy(float* dst, const float* src, int n, int tid) {
    for (int i = tid; i < n; i += 256) dst[i] = src[i];
}

__device__ __forceinline__ void layer64(const float* __restrict__ sw, const float* __restrict__ sb,
                                        const u64* __restrict__ in2, u64* __restrict__ out2) {
#pragma unroll 1
    for (int c0 = 0; c0 < 64; c0 += 8) {
        u64 acc[8];
#pragma unroll
        for (int u = 0; u < 8; u++) acc[u] = pack2(sb[c0 + u], 0.0f);
#pragma unroll 4
        for (int j4 = 0; j4 < 16; j4++) {
            u64 a0 = in2[2 * j4], a1 = in2[2 * j4 + 1];
#pragma unroll
            for (int u = 0; u < 8; u++) {
                ulonglong2 ww = *reinterpret_cast<const ulonglong2*>(&sw[(c0 + u) * 64 + 4 * j4]);
                acc[u] = fma2(ww.x, a0, acc[u]);
                acc[u] = fma2(ww.y, a1, acc[u]);
            }
        }
        float r[8];
#pragma unroll
        for (int u = 0; u < 8; u++) { float2 s = unpack2(acc[u]); r[u] = fmaxf(s.x + s.y, 0.0f); }
#pragma unroll
        for (int j = 0; j < 4; j++) out2[(c0 >> 1) + j] = pack2(r[2 * j], r[2 * j + 1]);
    }
}

__global__ __launch_bounds__(256, 1)
void kA(const float* __restrict__ points,
        const float* __restrict__ wl0, const float* __restrict__ bl0,
        const float* __restrict__ wl1, const float* __restrict__ bl1,
        const float* __restrict__ wl2, const float* __restrict__ bl2,
        const float* __restrict__ wl3, const float* __restrict__ bl3) {
    extern __shared__ float sm[];
    const int tid = threadIdx.x;
    smcpy(sm + 0,     wl0, 448,  tid);
    smcpy(sm + 448,   bl0, 64,   tid);
    smcpy(sm + 512,   wl1, 4096, tid);
    smcpy(sm + 4608,  bl1, 64,   tid);
    smcpy(sm + 4672,  wl2, 4096, tid);
    smcpy(sm + 8768,  bl2, 64,   tid);
    smcpy(sm + 8832,  wl3, 8192, tid);
    smcpy(sm + 17024, bl3, 128,  tid);
    __syncthreads();

    const int p = blockIdx.x * 256 + tid;
    const int b = p >> 14;
    const int i = p & (NPTS - 1);
    const float* pt = points + (size_t)b * INC * NPTS + i;
    float x[INC];
#pragma unroll
    for (int c = 0; c < INC; c++) x[c] = pt[(size_t)c * NPTS];

    int g = 0; float bv = x[3];
    if (x[4] > bv) { bv = x[4]; g = 1; }
    if (x[5] > bv) { bv = x[5]; g = 2; }
    if (x[6] > bv) { bv = x[6]; g = 3; }
    g_gid[p] = (unsigned char)g;

    // L0: 7 -> 64 into packed regs
    u64 a2[32], b2[32];
    {
        const float* w0 = sm; const float* bb0 = sm + 448;
#pragma unroll 4
        for (int j = 0; j < 32; j++) {
            float r0 = bb0[2 * j], r1 = bb0[2 * j + 1];
            const float* wr0 = w0 + (2 * j) * 7;
            const float* wr1 = wr0 + 7;
#pragma unroll
            for (int k = 0; k < 7; k++) { r0 = fmaf(wr0[k], x[k], r0); r1 = fmaf(wr1[k], x[k], r1); }
            a2[j] = pack2(fmaxf(r0, 0.0f), fmaxf(r1, 0.0f));
        }
    }
    layer64(sm + 512,  sm + 4608, a2, b2);   // L1
    layer64(sm + 4672, sm + 8768, b2, a2);   // L2

    // L3: 64 -> 128, store (b, c, i) coalesced
    const float* w3 = sm + 8832;
    const float* b3 = sm + 17024;
    float* op = g_h4 + (size_t)b * 128 * NPTS + i;
#pragma unroll 1
    for (int c0 = 0; c0 < 128; c0 += 8) {
        u64 acc[8];
#pragma unroll
        for (int u = 0; u < 8; u++) acc[u] = pack2(b3[c0 + u], 0.0f);
#pragma unroll 4
        for (int j4 = 0; j4 < 16; j4++) {
            u64 a0 = a2[2 * j4], a1 = a2[2 * j4 + 1];
#pragma unroll
            for (int u = 0; u < 8; u++) {
                ulonglong2 ww = *reinterpret_cast<const ulonglong2*>(&w3[(c0 + u) * 64 + 4 * j4]);
                acc[u] = fma2(ww.x, a0, acc[u]);
                acc[u] = fma2(ww.y, a1, acc[u]);
            }
        }
#pragma unroll
        for (int u = 0; u < 8; u++) {
            float2 s = unpack2(acc[u]);
            op[(size_t)(c0 + u) * NPTS] = fmaxf(s.x + s.y, 0.0f);
        }
    }
}

// ---------------- kernel B: 128 -> 1024 GEMM (FFMA2, k-paired) + fused reductions ----------------
#define WSTR 132
#define HSTR 130
#define KB_SMEM_FLOATS (128 * WSTR + 128 * HSTR)

__global__ __launch_bounds__(256, 1)
void kB(const float* __restrict__ wl4, const float* __restrict__ bl4) {
    extern __shared__ float sm[];
    float* ws = sm;                  // [c][k], stride 132
    float* hs = sm + 128 * WSTR;     // [p][k], stride 130
    __shared__ unsigned char gid_s[128];

    const int tid = threadIdx.x;
    const int tx = tid & 15;
    const int ty = tid >> 4;
    const int bid = blockIdx.x;
    const int b  = bid >> 6;
    const int cc = (bid >> 3) & 7;
    const int pb = bid & 7;
    const int c0 = cc * 128;
    const int pbase0 = pb * 2048;

#pragma unroll
    for (int j = 0; j < 16; j++) {
        int f4 = tid + 256 * j;
        int c = f4 >> 5, kf = (f4 & 31) * 4;
        float4 v = *reinterpret_cast<const float4*>(wl4 + (size_t)(c0 + c) * 128 + kf);
        *reinterpret_cast<float4*>(&ws[c * WSTR + kf]) = v;
    }
    float biasr[8];
#pragma unroll
    for (int u = 0; u < 8; u++) biasr[u] = bl4[c0 + ty * 8 + u];

    u64 pk[8];
    float gm[8][4];
#pragma unroll
    for (int u = 0; u < 8; u++) {
        pk[u] = 0ull;
#pragma unroll
        for (int g = 0; g < 4; g++) gm[u][g] = 0.0f;
    }

    const u64* wp = reinterpret_cast<const u64*>(ws) + (size_t)(ty * 8) * 66;   // WSTR/2
    const u64* hp = reinterpret_cast<const u64*>(hs) + (size_t)tx * 65;         // HSTR/2

#pragma unroll 1
    for (int tile = 0; tile < 16; tile++) {
        __syncthreads();
        const int pbase = pbase0 + tile * 128;
        // transpose-load h tile: coalesced LDG, scatter STS into [p][k]
#pragma unroll
        for (int j = 0; j < 16; j++) {
            int f4 = tid + 256 * j;
            int k = f4 >> 5, pp = (f4 & 31) * 4;
            float4 v = *reinterpret_cast<const float4*>(
                g_h4 + ((size_t)b * 128 + k) * NPTS + pbase + pp);
            hs[(pp + 0) * HSTR + k] = v.x;
            hs[(pp + 1) * HSTR + k] = v.y;
            hs[(pp + 2) * HSTR + k] = v.z;
            hs[(pp + 3) * HSTR + k] = v.w;
        }
        if (tid < 128) gid_s[tid] = g_gid[b * NPTS + pbase + tid];
        __syncthreads();

        u64 acc[8][8];
#pragma unroll
        for (int u = 0; u < 8; u++)
#pragma unroll
            for (int v = 0; v < 8; v++) acc[u][v] = 0ull;

#pragma unroll 2
        for (int k2 = 0; k2 < 64; k2++) {
            u64 hv[8];
#pragma unroll
            for (int v = 0; v < 8; v++) hv[v] = hp[v * 1040 + k2];   // 16*65
#pragma unroll
            for (int u = 0; u < 8; u++) {
                u64 w = wp[u * 66 + k2];
#pragma unroll
                for (int v = 0; v < 8; v++) acc[u][v] = fma2(w, hv[v], acc[u][v]);
            }
        }

        // epilogue: bias + relu + running reductions
#pragma unroll
        for (int v = 0; v < 8; v++) {
            const int plocal = tx + 16 * v;
            const int gi = gid_s[plocal];
            const u64 lowkey = (u64)(0xFFFFFFFFu - (unsigned int)(pbase + plocal));
#pragma unroll
            for (int u = 0; u < 8; u++) {
                float2 s = unpack2(acc[u][v]);
                float val = fmaxf(s.x + s.y + biasr[u], 0.0f);
                u64 key = ((u64)__float_as_uint(val) << 32) | lowkey;
                if (key > pk[u]) pk[u] = key;
#pragma unroll
                for (int g = 0; g < 4; g++)
                    gm[u][g] = fmaxf(gm[u][g], (gi == g) ? val : 0.0f);
            }
        }
    }

    // half-warp (16-lane) shuffle reduce over tx, then atomics
#pragma unroll
    for (int u = 0; u < 8; u++) {
        u64 m = pk[u];
        float mg0 = gm[u][0], mg1 = gm[u][1], mg2 = gm[u][2], mg3 = gm[u][3];
#pragma unroll
        for (int off = 8; off; off >>= 1) {
            u64 o = __shfl_xor_sync(0xFFFFFFFFu, m, off);
            if (o > m) m = o;
            mg0 = fmaxf(mg0, __shfl_xor_sync(0xFFFFFFFFu, mg0, off));
            mg1 = fmaxf(mg1, __shfl_xor_sync(0xFFFFFFFFu, mg1, off));
            mg2 = fmaxf(mg2, __shfl_xor_sync(0xFFFFFFFFu, mg2, off));
            mg3 = fmaxf(mg3, __shfl_xor_sync(0xFFFFFFFFu, mg3, off));
        }
        if (tx == 0) {
            int c = c0 + ty * 8 + u;
            atomicMax(&g_pmax[b * 1024 + c], m);
            atomicMax(&g_gmax[0 * 1024 + c], __float_as_uint(mg0));
            atomicMax(&g_gmax[1 * 1024 + c], __float_as_uint(mg1));
            atomicMax(&g_gmax[2 * 1024 + c], __float_as_uint(mg2));
            atomicMax(&g_gmax[3 * 1024 + c], __float_as_uint(mg3));
        }
    }
}

// ---------------- init + tail MLPs ----------------
__global__ void kInit() {
    int t = blockIdx.x * blockDim.x + threadIdx.x;
    if (t < BATCH * 1024) g_pmax[t] = 0ull;
    if (t < 4 * 1024) g_gmax[t] = 0u;
}

__global__ void kC1(const float* __restrict__ wg0, const float* __restrict__ bg0,
                    const float* __restrict__ wgr0, const float* __restrict__ bgr0,
                    float* __restrict__ out) {
    const int gtid = blockIdx.x * blockDim.x + threadIdx.x;
    if (gtid < BATCH * 1024) {
        unsigned long long pv = g_pmax[gtid];
        out[4096 + gtid] = (float)(0xFFFFFFFFu - (unsigned int)(pv & 0xFFFFFFFFull));
    }
    const int wid = gtid >> 5;
    const int lane = gtid & 31;
    const int row = wid >> 9;
    const int j = wid & 511;
    if (row > 16) return;
    float s = 0.0f;
    if (row < 16) {
        const float* wr = wg0 + (size_t)j * 1024;
        const unsigned long long* pbuf = g_pmax + row * 1024;
        for (int k = lane; k < 1024; k += 32)
            s = fmaf(wr[k], __uint_as_float((unsigned int)(pbuf[k] >> 32)), s);
    } else {
        const float* wr = wgr0 + (size_t)j * 4096;
        for (int k = lane; k < 4096; k += 32)
            s = fmaf(wr[k], __uint_as_float(g_gmax[k]), s);
    }
#pragma unroll
    for (int o = 16; o; o >>= 1) s += __shfl_xor_sync(0xFFFFFFFFu, s, o);
    if (lane == 0) {
        float bb = (row < 16) ? bg0[j] : bgr0[j];
        g_u1[row * 512 + j] = fmaxf(s + bb, 0.0f);
    }
}

__global__ void kC2(const float* __restrict__ wg1, const float* __restrict__ bg1,
                    const float* __restrict__ wgr1, const float* __restrict__ bgr1,
                    float* __restrict__ out) {
    const int gtid = blockIdx.x * blockDim.x + threadIdx.x;
    const int wid = gtid >> 5;
    const int lane = gtid & 31;
    const int row = wid >> 7;
    const int j = wid & 127;
    if (row > 16) return;
    const float* wr = ((row < 16) ? wg1 : wgr1) + (size_t)j * 512;
    const float* in = g_u1 + row * 512;
    float s = 0.0f;
    for (int k = lane; k < 512; k += 32) s = fmaf(wr[k], in[k], s);
#pragma unroll
    for (int o = 16; o; o >>= 1) s += __shfl_xor_sync(0xFFFFFFFFu, s, o);
    s = __shfl_sync(0xFFFFFFFFu, s, 0);
    float bb = (row < 16) ? bg1[j] : bgr1[j];
    float val = fmaxf(s + bb, 0.0f);
    if (row < 16) {
        if (lane == 0) out[row * 256 + 128 + j] = val;
    } else {
        if (lane < 16) out[lane * 256 + j] = val;
    }
}

// ---------------- launch ----------------
extern "C" void kernel_launch(void* const* d_in, const int* in_sizes, int n_in,
                              void* d_out, int out_size) {
    const float* points = (const float*)d_in[0];
    const float* wl0 = (const float*)d_in[1];  const float* bl0 = (const float*)d_in[2];
    const float* wl1 = (const float*)d_in[3];  const float* bl1 = (const float*)d_in[4];
    const float* wl2 = (const float*)d_in[5];  const float* bl2 = (const float*)d_in[6];
    const float* wl3 = (const float*)d_in[7];  const float* bl3 = (const float*)d_in[8];
    const float* wl4 = (const float*)d_in[9];  const float* bl4 = (const float*)d_in[10];
    const float* wg0 = (const float*)d_in[11]; const float* bg0 = (const float*)d_in[12];
    const float* wg1 = (const float*)d_in[13]; const float* bg1 = (const float*)d_in[14];
    const float* wgr0 = (const float*)d_in[15]; const float* bgr0 = (const float*)d_in[16];
    const float* wgr1 = (const float*)d_in[17]; const float* bgr1 = (const float*)d_in[18];
    float* out = (float*)d_out;

    cudaFuncSetAttribute(kA, cudaFuncAttributeMaxDynamicSharedMemorySize,
                         KA_SMEM_FLOATS * (int)sizeof(float));
    cudaFuncSetAttribute(kB, cudaFuncAttributeMaxDynamicSharedMemorySize,
                         KB_SMEM_FLOATS * (int)sizeof(float));

    kInit<<<64, 256>>>();
    kA<<<(BATCH * NPTS) / 256, 256, KA_SMEM_FLOATS * sizeof(float)>>>(
        points, wl0, bl0, wl1, bl1, wl2, bl2, wl3, bl3);
    kB<<<1024, 256, KB_SMEM_FLOATS * sizeof(float)>>>(wl4, bl4);
    kC1<<<1088, 256>>>(wg0, bg0, wgr0, bgr0, out);
    kC2<<<272, 256>>>(wg1, bg1, wgr1, bgr1, out);
}

// round 4
// speedup vs baseline: 1.0001x; 1.0001x over previous
#include <cuda_runtime.h>
#include <cstdint>

#define NPTS 16384
#define BATCH 16
#define INC 7

typedef unsigned long long u64;

__device__ __forceinline__ u64 fma2(u64 a, u64 b, u64 c) {
    u64 d; asm("fma.rn.f32x2 %0, %1, %2, %3;" : "=l"(d) : "l"(a), "l"(b), "l"(c)); return d;
}
__device__ __forceinline__ u64 pack2(float x, float y) {
    u64 r; asm("mov.b64 %0, {%1, %2};" : "=l"(r) : "f"(x), "f"(y)); return r;
}
__device__ __forceinline__ float2 unpack2(u64 p) {
    float2 v; asm("mov.b64 {%0, %1}, %2;" : "=f"(v.x), "=f"(v.y) : "l"(p)); return v;
}

// ---------------- scratch ----------------
__device__ float              g_h4[(size_t)BATCH * 128 * NPTS]; // (b, c, i)
__device__ unsigned char      g_gid[BATCH * NPTS];
__device__ unsigned long long g_pmax[BATCH * 1024];  // (valbits<<32)|(~idx)
__device__ unsigned int       g_gmax[4 * 1024];
__device__ float              g_u1[17 * 512];

// ---------------- kernel A: fused 7->64->64->64->128, register-resident ----------------
// smem = weights only:
//  w0:0(448) b0:448(64) w1:512(4096) b1:4608(64) w2:4672(4096) b2:8768(64)
//  w3:8832(8192) b3:17024(128)
#define KA_SMEM_FLOATS 17152

__device__ __forceinline__ void smcpy(float* dst, const float* src, int n, int tid) {
    for (int i = tid; i < n; i += 256) dst[i] = src[i];
}

__device__ __forceinline__ void layer64(const float* __restrict__ sw, const float* __restrict__ sb,
                                        const u64* __restrict__ in2, u64* __restrict__ out2) {
#pragma unroll 1
    for (int c0 = 0; c0 < 64; c0 += 8) {
        u64 acc[8];
#pragma unroll
        for (int u = 0; u < 8; u++) acc[u] = pack2(sb[c0 + u], 0.0f);
#pragma unroll 4
        for (int j4 = 0; j4 < 16; j4++) {
            u64 a0 = in2[2 * j4], a1 = in2[2 * j4 + 1];
#pragma unroll
            for (int u = 0; u < 8; u++) {
                ulonglong2 ww = *reinterpret_cast<const ulonglong2*>(&sw[(c0 + u) * 64 + 4 * j4]);
                acc[u] = fma2(ww.x, a0, acc[u]);
                acc[u] = fma2(ww.y, a1, acc[u]);
            }
        }
        float r[8];
#pragma unroll
        for (int u = 0; u < 8; u++) { float2 s = unpack2(acc[u]); r[u] = fmaxf(s.x + s.y, 0.0f); }
#pragma unroll
        for (int j = 0; j < 4; j++) out2[(c0 >> 1) + j] = pack2(r[2 * j], r[2 * j + 1]);
    }
}

__global__ __launch_bounds__(256, 1)
void kA(const float* __restrict__ points,
        const float* __restrict__ wl0, const float* __restrict__ bl0,
        const float* __restrict__ wl1, const float* __restrict__ bl1,
        const float* __restrict__ wl2, const float* __restrict__ bl2,
        const float* __restrict__ wl3, const float* __restrict__ bl3) {
    extern __shared__ float sm[];
    const int tid = threadIdx.x;
    smcpy(sm + 0,     wl0, 448,  tid);
    smcpy(sm + 448,   bl0, 64,   tid);
    smcpy(sm + 512,   wl1, 4096, tid);
    smcpy(sm + 4608,  bl1, 64,   tid);
    smcpy(sm + 4672,  wl2, 4096, tid);
    smcpy(sm + 8768,  bl2, 64,   tid);
    smcpy(sm + 8832,  wl3, 8192, tid);
    smcpy(sm + 17024, bl3, 128,  tid);
    __syncthreads();

    const int p = blockIdx.x * 256 + tid;
    const int b = p >> 14;
    const int i = p & (NPTS - 1);
    const float* pt = points + (size_t)b * INC * NPTS + i;
    float x[INC];
#pragma unroll
    for (int c = 0; c < INC; c++) x[c] = pt[(size_t)c * NPTS];

    int g = 0; float bv = x[3];
    if (x[4] > bv) { bv = x[4]; g = 1; }
    if (x[5] > bv) { bv = x[5]; g = 2; }
    if (x[6] > bv) { bv = x[6]; g = 3; }
    g_gid[p] = (unsigned char)g;

    // L0: 7 -> 64 into packed regs
    u64 a2[32], b2[32];
    {
        const float* w0 = sm; const float* bb0 = sm + 448;
#pragma unroll 4
        for (int j = 0; j < 32; j++) {
            float r0 = bb0[2 * j], r1 = bb0[2 * j + 1];
            const float* wr0 = w0 + (2 * j) * 7;
            const float* wr1 = wr0 + 7;
#pragma unroll
            for (int k = 0; k < 7; k++) { r0 = fmaf(wr0[k], x[k], r0); r1 = fmaf(wr1[k], x[k], r1); }
            a2[j] = pack2(fmaxf(r0, 0.0f), fmaxf(r1, 0.0f));
        }
    }
    layer64(sm + 512,  sm + 4608, a2, b2);   // L1
    layer64(sm + 4672, sm + 8768, b2, a2);   // L2

    // L3: 64 -> 128, store (b, c, i) coalesced
    const float* w3 = sm + 8832;
    const float* b3 = sm + 17024;
    float* op = g_h4 + (size_t)b * 128 * NPTS + i;
#pragma unroll 1
    for (int c0 = 0; c0 < 128; c0 += 8) {
        u64 acc[8];
#pragma unroll
        for (int u = 0; u < 8; u++) acc[u] = pack2(b3[c0 + u], 0.0f);
#pragma unroll 4
        for (int j4 = 0; j4 < 16; j4++) {
            u64 a0 = a2[2 * j4], a1 = a2[2 * j4 + 1];
#pragma unroll
            for (int u = 0; u < 8; u++) {
                ulonglong2 ww = *reinterpret_cast<const ulonglong2*>(&w3[(c0 + u) * 64 + 4 * j4]);
                acc[u] = fma2(ww.x, a0, acc[u]);
                acc[u] = fma2(ww.y, a1, acc[u]);
            }
        }
#pragma unroll
        for (int u = 0; u < 8; u++) {
            float2 s = unpack2(acc[u]);
            op[(size_t)(c0 + u) * NPTS] = fmaxf(s.x + s.y, 0.0f);
        }
    }
}

// ---------------- kernel B: 128 -> 1024 GEMM (FFMA2, k-paired) + fused reductions ----------------
#define WSTR 132
#define HSTR 130
#define KB_SMEM_FLOATS (128 * WSTR + 128 * HSTR)

__global__ __launch_bounds__(256, 1)
void kB(const float* __restrict__ wl4, const float* __restrict__ bl4) {
    extern __shared__ float sm[];
    float* ws = sm;                  // [c][k], stride 132
    float* hs = sm + 128 * WSTR;     // [p][k], stride 130
    __shared__ unsigned char gid_s[128];

    const int tid = threadIdx.x;
    const int tx = tid & 15;
    const int ty = tid >> 4;
    const int bid = blockIdx.x;
    const int b  = bid >> 6;
    const int cc = (bid >> 3) & 7;
    const int pb = bid & 7;
    const int c0 = cc * 128;
    const int pbase0 = pb * 2048;

#pragma unroll
    for (int j = 0; j < 16; j++) {
        int f4 = tid + 256 * j;
        int c = f4 >> 5, kf = (f4 & 31) * 4;
        float4 v = *reinterpret_cast<const float4*>(wl4 + (size_t)(c0 + c) * 128 + kf);
        *reinterpret_cast<float4*>(&ws[c * WSTR + kf]) = v;
    }
    float biasr[8];
#pragma unroll
    for (int u = 0; u < 8; u++) biasr[u] = bl4[c0 + ty * 8 + u];

    u64 pk[8];
    float gm[8][4];
#pragma unroll
    for (int u = 0; u < 8; u++) {
        pk[u] = 0ull;
#pragma unroll
        for (int g = 0; g < 4; g++) gm[u][g] = 0.0f;
    }

    const u64* wp = reinterpret_cast<const u64*>(ws) + (size_t)(ty * 8) * 66;   // WSTR/2
    const u64* hp = reinterpret_cast<const u64*>(hs) + (size_t)tx * 65;         // HSTR/2

#pragma unroll 1
    for (int tile = 0; tile < 16; tile++) {
        __syncthreads();
        const int pbase = pbase0 + tile * 128;
        // transpose-load h tile: coalesced LDG, scatter STS into [p][k]
#pragma unroll
        for (int j = 0; j < 16; j++) {
            int f4 = tid + 256 * j;
            int k = f4 >> 5, pp = (f4 & 31) * 4;
            float4 v = *reinterpret_cast<const float4*>(
                g_h4 + ((size_t)b * 128 + k) * NPTS + pbase + pp);
            hs[(pp + 0) * HSTR + k] = v.x;
            hs[(pp + 1) * HSTR + k] = v.y;
            hs[(pp + 2) * HSTR + k] = v.z;
            hs[(pp + 3) * HSTR + k] = v.w;
        }
        if (tid < 128) gid_s[tid] = g_gid[b * NPTS + pbase + tid];
        __syncthreads();

        u64 acc[8][8];
#pragma unroll
        for (int u = 0; u < 8; u++)
#pragma unroll
            for (int v = 0; v < 8; v++) acc[u][v] = 0ull;

#pragma unroll 2
        for (int k2 = 0; k2 < 64; k2++) {
            u64 hv[8];
#pragma unroll
            for (int v = 0; v < 8; v++) hv[v] = hp[v * 1040 + k2];   // 16*65
#pragma unroll
            for (int u = 0; u < 8; u++) {
                u64 w = wp[u * 66 + k2];
#pragma unroll
                for (int v = 0; v < 8; v++) acc[u][v] = fma2(w, hv[v], acc[u][v]);
            }
        }

        // epilogue: bias + relu + running reductions
#pragma unroll
        for (int v = 0; v < 8; v++) {
            const int plocal = tx + 16 * v;
            const int gi = gid_s[plocal];
            const u64 lowkey = (u64)(0xFFFFFFFFu - (unsigned int)(pbase + plocal));
#pragma unroll
            for (int u = 0; u < 8; u++) {
                float2 s = unpack2(acc[u][v]);
                float val = fmaxf(s.x + s.y + biasr[u], 0.0f);
                u64 key = ((u64)__float_as_uint(val) << 32) | lowkey;
                if (key > pk[u]) pk[u] = key;
#pragma unroll
                for (int g = 0; g < 4; g++)
                    gm[u][g] = fmaxf(gm[u][g], (gi == g) ? val : 0.0f);
            }
        }
    }

    // half-warp (16-lane) shuffle reduce over tx, then atomics
#pragma unroll
    for (int u = 0; u < 8; u++) {
        u64 m = pk[u];
        float mg0 = gm[u][0], mg1 = gm[u][1], mg2 = gm[u][2], mg3 = gm[u][3];
#pragma unroll
        for (int off = 8; off; off >>= 1) {
            u64 o = __shfl_xor_sync(0xFFFFFFFFu, m, off);
            if (o > m) m = o;
            mg0 = fmaxf(mg0, __shfl_xor_sync(0xFFFFFFFFu, mg0, off));
            mg1 = fmaxf(mg1, __shfl_xor_sync(0xFFFFFFFFu, mg1, off));
            mg2 = fmaxf(mg2, __shfl_xor_sync(0xFFFFFFFFu, mg2, off));
            mg3 = fmaxf(mg3, __shfl_xor_sync(0xFFFFFFFFu, mg3, off));
        }
        if (tx == 0) {
            int c = c0 + ty * 8 + u;
            atomicMax(&g_pmax[b * 1024 + c], m);
            atomicMax(&g_gmax[0 * 1024 + c], __float_as_uint(mg0));
            atomicMax(&g_gmax[1 * 1024 + c], __float_as_uint(mg1));
            atomicMax(&g_gmax[2 * 1024 + c], __float_as_uint(mg2));
            atomicMax(&g_gmax[3 * 1024 + c], __float_as_uint(mg3));
        }
    }
}

// ---------------- init + tail MLPs ----------------
__global__ void kInit() {
    int t = blockIdx.x * blockDim.x + threadIdx.x;
    if (t < BATCH * 1024) g_pmax[t] = 0ull;
    if (t < 4 * 1024) g_gmax[t] = 0u;
}

__global__ void kC1(const float* __restrict__ wg0, const float* __restrict__ bg0,
                    const float* __restrict__ wgr0, const float* __restrict__ bgr0,
                    float* __restrict__ out) {
    const int gtid = blockIdx.x * blockDim.x + threadIdx.x;
    if (gtid < BATCH * 1024) {
        unsigned long long pv = g_pmax[gtid];
        out[4096 + gtid] = (float)(0xFFFFFFFFu - (unsigned int)(pv & 0xFFFFFFFFull));
    }
    const int wid = gtid >> 5;
    const int lane = gtid & 31;
    const int row = wid >> 9;
    const int j = wid & 511;
    if (row > 16) return;
    float s = 0.0f;
    if (row < 16) {
        const float* wr = wg0 + (size_t)j * 1024;
        const unsigned long long* pbuf = g_pmax + row * 1024;
        for (int k = lane; k < 1024; k += 32)
            s = fmaf(wr[k], __uint_as_float((unsigned int)(pbuf[k] >> 32)), s);
    } else {
        const float* wr = wgr0 + (size_t)j * 4096;
        for (int k = lane; k < 4096; k += 32)
            s = fmaf(wr[k], __uint_as_float(g_gmax[k]), s);
    }
#pragma unroll
    for (int o = 16; o; o >>= 1) s += __shfl_xor_sync(0xFFFFFFFFu, s, o);
    if (lane == 0) {
        float bb = (row < 16) ? bg0[j] : bgr0[j];
        g_u1[row * 512 + j] = fmaxf(s + bb, 0.0f);
    }
}

__global__ void kC2(const float* __restrict__ wg1, const float* __restrict__ bg1,
                    const float* __restrict__ wgr1, const float* __restrict__ bgr1,
                    float* __restrict__ out) {
    const int gtid = blockIdx.x * blockDim.x + threadIdx.x;
    const int wid = gtid >> 5;
    const int lane = gtid & 31;
    const int row = wid >> 7;
    const int j = wid & 127;
    if (row > 16) return;
    const float* wr = ((row < 16) ? wg1 : wgr1) + (size_t)j * 512;
    const float* in = g_u1 + row * 512;
    float s = 0.0f;
    for (int k = lane; k < 512; k += 32) s = fmaf(wr[k], in[k], s);
#pragma unroll
    for (int o = 16; o; o >>= 1) s += __shfl_xor_sync(0xFFFFFFFFu, s, o);
    s = __shfl_sync(0xFFFFFFFFu, s, 0);
    float bb = (row < 16) ? bg1[j] : bgr1[j];
    float val = fmaxf(s + bb, 0.0f);
    if (row < 16) {
        if (lane == 0) out[row * 256 + 128 + j] = val;
    } else {
        if (lane < 16) out[lane * 256 + j] = val;
    }
}

// ---------------- launch ----------------
extern "C" void kernel_launch(void* const* d_in, const int* in_sizes, int n_in,
                              void* d_out, int out_size) {
    const float* points = (const float*)d_in[0];
    const float* wl0 = (const float*)d_in[1];  const float* bl0 = (const float*)d_in[2];
    const float* wl1 = (const float*)d_in[3];  const float* bl1 = (const float*)d_in[4];
    const float* wl2 = (const float*)d_in[5];  const float* bl2 = (const float*)d_in[6];
    const float* wl3 = (const float*)d_in[7];  const float* bl3 = (const float*)d_in[8];
    const float* wl4 = (const float*)d_in[9];  const float* bl4 = (const float*)d_in[10];
    const float* wg0 = (const float*)d_in[11]; const float* bg0 = (const float*)d_in[12];
    const float* wg1 = (const float*)d_in[13]; const float* bg1 = (const float*)d_in[14];
    const float* wgr0 = (const float*)d_in[15]; const float* bgr0 = (const float*)d_in[16];
    const float* wgr1 = (const float*)d_in[17]; const float* bgr1 = (const float*)d_in[18];
    float* out = (float*)d_out;

    cudaFuncSetAttribute(kA, cudaFuncAttributeMaxDynamicSharedMemorySize,
                         KA_SMEM_FLOATS * (int)sizeof(float));
    cudaFuncSetAttribute(kB, cudaFuncAttributeMaxDynamicSharedMemorySize,
                         KB_SMEM_FLOATS * (int)sizeof(float));

    kInit<<<64, 256>>>();
    kA<<<(BATCH * NPTS) / 256, 256, KA_SMEM_FLOATS * sizeof(float)>>>(
        points, wl0, bl0, wl1, bl1, wl2, bl2, wl3, bl3);
    kB<<<1024, 256, KB_SMEM_FLOATS * sizeof(float)>>>(wl4, bl4);
    kC1<<<1088, 256>>>(wg0, bg0, wgr0, bgr0, out);
    kC2<<<272, 256>>>(wg1, bg1, wgr1, bgr1, out);
}

// round 6
// speedup vs baseline: 1.3754x; 1.3753x over previous
#include <cuda_runtime.h>
#include <cstdint>

#define NPTS 16384
#define BATCH 16
#define INC 7
typedef unsigned long long u64;
typedef unsigned int u32;

// ---------------- scratch ----------------
__device__ float              g_h4[(size_t)BATCH * 128 * NPTS]; // (b, c, i)
__device__ unsigned char      g_gid[BATCH * NPTS];
__device__ unsigned long long g_pmax[BATCH * 1024];  // (valbits<<32)|(~idx)
__device__ unsigned int       g_gmax[4 * 1024];
__device__ float              g_u1[17 * 512];

__device__ __forceinline__ float cvt_tf32(float v) {
    float r; asm("cvt.rn.tf32.f32 %0, %1;" : "=f"(r) : "f"(v)); return r;
}
__device__ __forceinline__ void mma8(float* d, const float* a, const float* bb) {
    asm volatile("mma.sync.aligned.m16n8k8.row.col.f32.tf32.tf32.f32 "
                 "{%0,%1,%2,%3}, {%4,%5,%6,%7}, {%8,%9}, {%0,%1,%2,%3};"
                 : "+f"(d[0]), "+f"(d[1]), "+f"(d[2]), "+f"(d[3])
                 : "r"(__float_as_uint(a[0])), "r"(__float_as_uint(a[1])),
                   "r"(__float_as_uint(a[2])), "r"(__float_as_uint(a[3])),
                   "r"(__float_as_uint(bb[0])), "r"(__float_as_uint(bb[1])));
}

// ---------------- kernel A: fused 7->64->64->64->128 (R2 proven) ----------------
#define KA_SMEM_FLOATS (17152 + 2 * 16384)

__device__ __forceinline__ void smcpy(float* dst, const float* src, int n, int tid) {
    for (int i = tid; i < n; i += 256) dst[i] = src[i];
}
__device__ __forceinline__ void mlp64(const float* __restrict__ sw, const float* __restrict__ sb,
                                      const float* __restrict__ ain, float* __restrict__ aout, int tid) {
#pragma unroll 1
    for (int c0 = 0; c0 < 64; c0 += 8) {
        float acc[8];
#pragma unroll
        for (int u = 0; u < 8; u++) acc[u] = sb[c0 + u];
#pragma unroll 4
        for (int k = 0; k < 64; k += 4) {
            float a0 = ain[(k + 0) * 256 + tid];
            float a1 = ain[(k + 1) * 256 + tid];
            float a2 = ain[(k + 2) * 256 + tid];
            float a3 = ain[(k + 3) * 256 + tid];
#pragma unroll
            for (int u = 0; u < 8; u++) {
                float4 w4 = *reinterpret_cast<const float4*>(&sw[(c0 + u) * 64 + k]);
                acc[u] = fmaf(w4.x, a0, acc[u]);
                acc[u] = fmaf(w4.y, a1, acc[u]);
                acc[u] = fmaf(w4.z, a2, acc[u]);
                acc[u] = fmaf(w4.w, a3, acc[u]);
            }
        }
#pragma unroll
        for (int u = 0; u < 8; u++) aout[(c0 + u) * 256 + tid] = fmaxf(acc[u], 0.0f);
    }
}

__global__ __launch_bounds__(256, 1)
void kA(const float* __restrict__ points,
        const float* __restrict__ wl0, const float* __restrict__ bl0,
        const float* __restrict__ wl1, const float* __restrict__ bl1,
        const float* __restrict__ wl2, const float* __restrict__ bl2,
        const float* __restrict__ wl3, const float* __restrict__ bl3) {
    extern __shared__ float sm[];
    const int tid = threadIdx.x;
    smcpy(sm + 0,     wl0, 448,  tid);
    smcpy(sm + 448,   bl0, 64,   tid);
    smcpy(sm + 512,   wl1, 4096, tid);
    smcpy(sm + 4608,  bl1, 64,   tid);
    smcpy(sm + 4672,  wl2, 4096, tid);
    smcpy(sm + 8768,  bl2, 64,   tid);
    smcpy(sm + 8832,  wl3, 8192, tid);
    smcpy(sm + 17024, bl3, 128,  tid);
    float* hA = sm + 17152;
    float* hB = sm + 17152 + 16384;
    __syncthreads();

    const int p = blockIdx.x * 256 + tid;
    const int b = p >> 14;
    const int i = p & (NPTS - 1);
    const float* pt = points + (size_t)b * INC * NPTS + i;
    float x[INC];
#pragma unroll
    for (int c = 0; c < INC; c++) x[c] = pt[(size_t)c * NPTS];

    int g = 0; float bv = x[3];
    if (x[4] > bv) { bv = x[4]; g = 1; }
    if (x[5] > bv) { bv = x[5]; g = 2; }
    if (x[6] > bv) { bv = x[6]; g = 3; }
    g_gid[p] = (unsigned char)g;

#pragma unroll 1
    for (int c0 = 0; c0 < 64; c0 += 8) {
        float acc[8];
#pragma unroll
        for (int u = 0; u < 8; u++) {
            const float* wr = &sm[(c0 + u) * 7];
            float s = sm[448 + c0 + u];
#pragma unroll
            for (int k = 0; k < 7; k++) s = fmaf(wr[k], x[k], s);
            acc[u] = s;
        }
#pragma unroll
        for (int u = 0; u < 8; u++) hA[(c0 + u) * 256 + tid] = fmaxf(acc[u], 0.0f);
    }

    mlp64(sm + 512,  sm + 4608, hA, hB, tid);
    mlp64(sm + 4672, sm + 8768, hB, hA, tid);

    float* op = g_h4 + (size_t)b * 128 * NPTS + i;
    const float* sw3 = sm + 8832;
    const float* sb3 = sm + 17024;
#pragma unroll 1
    for (int c0 = 0; c0 < 128; c0 += 8) {
        float acc[8];
#pragma unroll
        for (int u = 0; u < 8; u++) acc[u] = sb3[c0 + u];
#pragma unroll 4
        for (int k = 0; k < 64; k += 4) {
            float a0 = hA[(k + 0) * 256 + tid];
            float a1 = hA[(k + 1) * 256 + tid];
            float a2 = hA[(k + 2) * 256 + tid];
            float a3 = hA[(k + 3) * 256 + tid];
#pragma unroll
            for (int u = 0; u < 8; u++) {
                float4 w4 = *reinterpret_cast<const float4*>(&sw3[(c0 + u) * 64 + k]);
                acc[u] = fmaf(w4.x, a0, acc[u]);
                acc[u] = fmaf(w4.y, a1, acc[u]);
                acc[u] = fmaf(w4.z, a2, acc[u]);
                acc[u] = fmaf(w4.w, a3, acc[u]);
            }
        }
#pragma unroll
        for (int u = 0; u < 8; u++) op[(size_t)(c0 + u) * NPTS] = fmaxf(acc[u], 0.0f);
    }
}

// ---------------- kernel B: 3-pass split-tf32 mma.sync GEMM + fused reductions ----------------
// smem: sw 128x132 fp32 (W tile) | sh 128x136 fp32 (H tile); staging reuses sw region
#define WS 132
#define HS 136
#define KB_SMEM_FLOATS (128 * WS + 128 * HS)

__global__ __launch_bounds__(256, 1)
void kB(const float* __restrict__ wl4, const float* __restrict__ bl4) {
    extern __shared__ float sm[];
    float* sw = sm;
    float* sh = sm + 128 * WS;
    __shared__ unsigned char gid_s[128];

    const int tid = threadIdx.x;
    const int bid = blockIdx.x;
    const int b  = bid >> 10;
    const int pb = (bid >> 3) & 127;     // pb outer of cc: 8 consecutive CTAs share the H tile in L2
    const int cc = bid & 7;
    const int c0 = cc * 128;
    const int pbase = pb * 128;

    // load W tile [c][k] fp32
#pragma unroll
    for (int j = 0; j < 16; j++) {
        int idx = j * 256 + tid;
        int r = idx >> 5, q = (idx & 31) * 4;
        float4 v = *reinterpret_cast<const float4*>(wl4 + (size_t)(c0 + r) * 128 + q);
        *reinterpret_cast<float4*>(&sw[r * WS + q]) = v;
    }
    // load H tile [k][p] fp32
#pragma unroll
    for (int j = 0; j < 16; j++) {
        int idx = j * 256 + tid;
        int k = idx >> 5, q = (idx & 31) * 4;
        float4 v = *reinterpret_cast<const float4*>(
            g_h4 + ((size_t)b * 128 + k) * NPTS + pbase + q);
        *reinterpret_cast<float4*>(&sh[k * HS + q]) = v;
    }
    if (tid < 128) gid_s[tid] = g_gid[b * NPTS + pbase + tid];
    __syncthreads();

    const int lane = tid & 31, wrp = tid >> 5;
    const int mw = wrp >> 1;            // 0..3: 32-channel slab
    const int nw = wrp & 1;             // 0..1: 64-point slab
    const int gid4 = lane >> 2, tig = lane & 3;
    const int cw = mw * 32, pw = nw * 64;

    float acc[2][8][4];
#pragma unroll
    for (int mt = 0; mt < 2; mt++)
#pragma unroll
        for (int nt = 0; nt < 8; nt++)
#pragma unroll
            for (int j = 0; j < 4; j++) acc[mt][nt][j] = 0.0f;

#pragma unroll 2
    for (int kk = 0; kk < 16; kk++) {
        const int kb = kk * 8;
        float ah[2][4], al[2][4];
#pragma unroll
        for (int mt = 0; mt < 2; mt++) {
            const int cb = cw + mt * 16;
            float x0 = sw[(cb + gid4) * WS + kb + tig];
            float x1 = sw[(cb + gid4 + 8) * WS + kb + tig];
            float x2 = sw[(cb + gid4) * WS + kb + tig + 4];
            float x3 = sw[(cb + gid4 + 8) * WS + kb + tig + 4];
            ah[mt][0] = cvt_tf32(x0); al[mt][0] = x0 - ah[mt][0];
            ah[mt][1] = cvt_tf32(x1); al[mt][1] = x1 - ah[mt][1];
            ah[mt][2] = cvt_tf32(x2); al[mt][2] = x2 - ah[mt][2];
            ah[mt][3] = cvt_tf32(x3); al[mt][3] = x3 - ah[mt][3];
        }
        float bh[8][2], bl[8][2];
#pragma unroll
        for (int nt = 0; nt < 8; nt++) {
            const int pp = pw + nt * 8 + gid4;
            float y0 = sh[(kb + tig) * HS + pp];
            float y1 = sh[(kb + tig + 4) * HS + pp];
            bh[nt][0] = cvt_tf32(y0); bl[nt][0] = y0 - bh[nt][0];
            bh[nt][1] = cvt_tf32(y1); bl[nt][1] = y1 - bh[nt][1];
        }
#pragma unroll
        for (int mt = 0; mt < 2; mt++)
#pragma unroll
            for (int nt = 0; nt < 8; nt++) {
                mma8(acc[mt][nt], ah[mt], bh[nt]);
                mma8(acc[mt][nt], ah[mt], bl[nt]);
                mma8(acc[mt][nt], al[mt], bh[nt]);
            }
    }

    // ---- epilogue: bias + relu + max/argmax/group-max ----
    __syncthreads();                    // smem W region free for staging now
    u64* skey = reinterpret_cast<u64*>(sm);          // 128*8 u64 = 8 KB
    float* sg = reinterpret_cast<float*>(skey + 1024); // 128*8*4 f32 = 16 KB
    const int slot = nw * 4 + tig;

#pragma unroll
    for (int mt = 0; mt < 2; mt++)
#pragma unroll
        for (int hf = 0; hf < 2; hf++) {
            const int c = cw + mt * 16 + gid4 + hf * 8;
            const float bias_c = __ldg(&bl4[c0 + c]);
            u64 key = 0ull;
            float g0 = 0.f, g1 = 0.f, g2 = 0.f, g3 = 0.f;
#pragma unroll
            for (int nt = 0; nt < 8; nt++)
#pragma unroll
                for (int jj = 0; jj < 2; jj++) {
                    float val = fmaxf(acc[mt][nt][hf * 2 + jj] + bias_c, 0.0f);
                    const int pl = pw + nt * 8 + tig * 2 + jj;
                    u64 k = ((u64)__float_as_uint(val) << 32) |
                            (u64)(0xFFFFFFFFu - (u32)(pbase + pl));
                    if (k > key) key = k;
                    const int gi = gid_s[pl];
                    g0 = fmaxf(g0, gi == 0 ? val : 0.f);
                    g1 = fmaxf(g1, gi == 1 ? val : 0.f);
                    g2 = fmaxf(g2, gi == 2 ? val : 0.f);
                    g3 = fmaxf(g3, gi == 3 ? val : 0.f);
                }
            skey[c * 8 + slot] = key;
            sg[(c * 8 + slot) * 4 + 0] = g0;
            sg[(c * 8 + slot) * 4 + 1] = g1;
            sg[(c * 8 + slot) * 4 + 2] = g2;
            sg[(c * 8 + slot) * 4 + 3] = g3;
        }
    __syncthreads();

    if (tid < 128) {
        const int c = tid;
        u64 m = skey[c * 8];
        float mg[4] = { sg[c * 32 + 0], sg[c * 32 + 1], sg[c * 32 + 2], sg[c * 32 + 3] };
#pragma unroll
        for (int t = 1; t < 8; t++) {
            u64 q = skey[c * 8 + t];
            if (q > m) m = q;
#pragma unroll
            for (int g = 0; g < 4; g++) mg[g] = fmaxf(mg[g], sg[(c * 8 + t) * 4 + g]);
        }
        atomicMax(&g_pmax[b * 1024 + c0 + c], m);
#pragma unroll
        for (int g = 0; g < 4; g++)
            atomicMax(&g_gmax[g * 1024 + c0 + c], __float_as_uint(mg[g]));
    }
}

// ---------------- init + tail MLPs (R2 proven) ----------------
__global__ void kInit() {
    int t = blockIdx.x * blockDim.x + threadIdx.x;
    if (t < BATCH * 1024) g_pmax[t] = 0ull;
    if (t < 4 * 1024) g_gmax[t] = 0u;
}

__global__ void kC1(const float* __restrict__ wg0, const float* __restrict__ bg0,
                    const float* __restrict__ wgr0, const float* __restrict__ bgr0,
                    float* __restrict__ out) {
    const int gtid = blockIdx.x * blockDim.x + threadIdx.x;
    if (gtid < BATCH * 1024) {
        unsigned long long pv = g_pmax[gtid];
        out[4096 + gtid] = (float)(0xFFFFFFFFu - (unsigned int)(pv & 0xFFFFFFFFull));
    }
    const int wid = gtid >> 5;
    const int lane = gtid & 31;
    const int row = wid >> 9;
    const int j = wid & 511;
    if (row > 16) return;
    float s = 0.0f;
    if (row < 16) {
        const float* wr = wg0 + (size_t)j * 1024;
        const unsigned long long* pbuf = g_pmax + row * 1024;
        for (int k = lane; k < 1024; k += 32)
            s = fmaf(wr[k], __uint_as_float((unsigned int)(pbuf[k] >> 32)), s);
    } else {
        const float* wr = wgr0 + (size_t)j * 4096;
        for (int k = lane; k < 4096; k += 32)
            s = fmaf(wr[k], __uint_as_float(g_gmax[k]), s);
    }
#pragma unroll
    for (int o = 16; o; o >>= 1) s += __shfl_xor_sync(0xFFFFFFFFu, s, o);
    if (lane == 0) {
        float bb = (row < 16) ? bg0[j] : bgr0[j];
        g_u1[row * 512 + j] = fmaxf(s + bb, 0.0f);
    }
}

__global__ void kC2(const float* __restrict__ wg1, const float* __restrict__ bg1,
                    const float* __restrict__ wgr1, const float* __restrict__ bgr1,
                    float* __restrict__ out) {
    const int gtid = blockIdx.x * blockDim.x + threadIdx.x;
    const int wid = gtid >> 5;
    const int lane = gtid & 31;
    const int row = wid >> 7;
    const int j = wid & 127;
    if (row > 16) return;
    const float* wr = ((row < 16) ? wg1 : wgr1) + (size_t)j * 512;
    const float* in = g_u1 + row * 512;
    float s = 0.0f;
    for (int k = lane; k < 512; k += 32) s = fmaf(wr[k], in[k], s);
#pragma unroll
    for (int o = 16; o; o >>= 1) s += __shfl_xor_sync(0xFFFFFFFFu, s, o);
    s = __shfl_sync(0xFFFFFFFFu, s, 0);
    float bb = (row < 16) ? bg1[j] : bgr1[j];
    float val = fmaxf(s + bb, 0.0f);
    if (row < 16) {
        if (lane == 0) out[row * 256 + 128 + j] = val;
    } else {
        if (lane < 16) out[lane * 256 + j] = val;
    }
}

// ---------------- launch ----------------
extern "C" void kernel_launch(void* const* d_in, const int* in_sizes, int n_in,
                              void* d_out, int out_size) {
    const float* points = (const float*)d_in[0];
    const float* wl0 = (const float*)d_in[1];  const float* bl0 = (const float*)d_in[2];
    const float* wl1 = (const float*)d_in[3];  const float* bl1 = (const float*)d_in[4];
    const float* wl2 = (const float*)d_in[5];  const float* bl2 = (const float*)d_in[6];
    const float* wl3 = (const float*)d_in[7];  const float* bl3 = (const float*)d_in[8];
    const float* wl4 = (const float*)d_in[9];  const float* bl4 = (const float*)d_in[10];
    const float* wg0 = (const float*)d_in[11]; const float* bg0 = (const float*)d_in[12];
    const float* wg1 = (const float*)d_in[13]; const float* bg1 = (const float*)d_in[14];
    const float* wgr0 = (const float*)d_in[15]; const float* bgr0 = (const float*)d_in[16];
    const float* wgr1 = (const float*)d_in[17]; const float* bgr1 = (const float*)d_in[18];
    float* out = (float*)d_out;

    cudaFuncSetAttribute(kA, cudaFuncAttributeMaxDynamicSharedMemorySize,
                         KA_SMEM_FLOATS * (int)sizeof(float));
    cudaFuncSetAttribute(kB, cudaFuncAttributeMaxDynamicSharedMemorySize,
                         KB_SMEM_FLOATS * (int)sizeof(float));

    kInit<<<64, 256>>>();
    kA<<<(BATCH * NPTS) / 256, 256, KA_SMEM_FLOATS * sizeof(float)>>>(
        points, wl0, bl0, wl1, bl1, wl2, bl2, wl3, bl3);
    kB<<<16384, 256, KB_SMEM_FLOATS * sizeof(float)>>>(wl4, bl4);
    kC1<<<1088, 256>>>(wg0, bg0, wgr0, bgr0, out);
    kC2<<<272, 256>>>(wg1, bg1, wgr1, bgr1, out);
}

// round 7
// speedup vs baseline: 1.4053x; 1.0217x over previous
#include <cuda_runtime.h>
#include <cstdint>

#define NPTS 16384
#define BATCH 16
#define INC 7
typedef unsigned long long u64;
typedef unsigned int u32;

// ---------------- scratch ----------------
__device__ float              g_h4[(size_t)BATCH * 128 * NPTS]; // (b, c, i)
__device__ unsigned char      g_gid[BATCH * NPTS];
__device__ unsigned long long g_pmax[BATCH * 1024];  // (valbits<<32)|(~idx)
__device__ unsigned int       g_gmax[4 * 1024];
__device__ float              g_u1[17 * 512];

__device__ __forceinline__ float cvt_tf32(float v) {
    float r; asm("cvt.rn.tf32.f32 %0, %1;" : "=f"(r) : "f"(v)); return r;
}
__device__ __forceinline__ void mma8(float* d, const float* a, const float* bb) {
    asm volatile("mma.sync.aligned.m16n8k8.row.col.f32.tf32.tf32.f32 "
                 "{%0,%1,%2,%3}, {%4,%5,%6,%7}, {%8,%9}, {%0,%1,%2,%3};"
                 : "+f"(d[0]), "+f"(d[1]), "+f"(d[2]), "+f"(d[3])
                 : "r"(__float_as_uint(a[0])), "r"(__float_as_uint(a[1])),
                   "r"(__float_as_uint(a[2])), "r"(__float_as_uint(a[3])),
                   "r"(__float_as_uint(bb[0])), "r"(__float_as_uint(bb[1])));
}
__device__ __forceinline__ u32 smem_u32(const void* p) {
    u32 a; asm("{ .reg .u64 t; cvta.to.shared.u64 t, %1; cvt.u32.u64 %0, t; }" : "=r"(a) : "l"(p)); return a;
}
#define CP_ASYNC16(dst, src) asm volatile("cp.async.cg.shared.global [%0], [%1], 16;" :: "r"(dst), "l"(src) : "memory")
#define CP_COMMIT()  asm volatile("cp.async.commit_group;" ::: "memory")
#define CP_WAIT0()   asm volatile("cp.async.wait_group 0;" ::: "memory")
#define CP_WAIT1()   asm volatile("cp.async.wait_group 1;" ::: "memory")

// ---------------- kernel A: fused 7->64->64->64->128, 128 thr, staged weights, 2 CTA/SM ----------------
// smem floats: wbuf 0..8320 | hA 8320..16512 | hB 16512..24704
#define KA_SMEM_FLOATS 24704

__device__ __forceinline__ void smcpy128(float* dst, const float* src, int n, int tid) {
    for (int i = tid; i < n; i += 128) dst[i] = src[i];
}
__device__ __forceinline__ void mlp64s(const float* __restrict__ sw, const float* __restrict__ sb,
                                       const float* __restrict__ ain, float* __restrict__ aout, int tid) {
#pragma unroll 1
    for (int c0 = 0; c0 < 64; c0 += 8) {
        float acc[8];
#pragma unroll
        for (int u = 0; u < 8; u++) acc[u] = sb[c0 + u];
#pragma unroll 4
        for (int k = 0; k < 64; k += 4) {
            float a0 = ain[(k + 0) * 128 + tid];
            float a1 = ain[(k + 1) * 128 + tid];
            float a2 = ain[(k + 2) * 128 + tid];
            float a3 = ain[(k + 3) * 128 + tid];
#pragma unroll
            for (int u = 0; u < 8; u++) {
                float4 w4 = *reinterpret_cast<const float4*>(&sw[(c0 + u) * 64 + k]);
                acc[u] = fmaf(w4.x, a0, acc[u]);
                acc[u] = fmaf(w4.y, a1, acc[u]);
                acc[u] = fmaf(w4.z, a2, acc[u]);
                acc[u] = fmaf(w4.w, a3, acc[u]);
            }
        }
#pragma unroll
        for (int u = 0; u < 8; u++) aout[(c0 + u) * 128 + tid] = fmaxf(acc[u], 0.0f);
    }
}

__global__ __launch_bounds__(128, 2)
void kA(const float* __restrict__ points,
        const float* __restrict__ wl0, const float* __restrict__ bl0,
        const float* __restrict__ wl1, const float* __restrict__ bl1,
        const float* __restrict__ wl2, const float* __restrict__ bl2,
        const float* __restrict__ wl3, const float* __restrict__ bl3) {
    extern __shared__ float sm[];
    float* wbuf = sm;
    float* hA = sm + 8320;
    float* hB = sm + 16512;
    const int tid = threadIdx.x;

    // phase 1: w0|b0|w1|b1
    smcpy128(wbuf + 0,    wl0, 448,  tid);
    smcpy128(wbuf + 448,  bl0, 64,   tid);
    smcpy128(wbuf + 512,  wl1, 4096, tid);
    smcpy128(wbuf + 4608, bl1, 64,   tid);

    const int p = blockIdx.x * 128 + tid;
    const int b = p >> 14;
    const int i = p & (NPTS - 1);
    const float* pt = points + (size_t)b * INC * NPTS + i;
    float x[INC];
#pragma unroll
    for (int c = 0; c < INC; c++) x[c] = pt[(size_t)c * NPTS];

    int g = 0; float bv = x[3];
    if (x[4] > bv) { bv = x[4]; g = 1; }
    if (x[5] > bv) { bv = x[5]; g = 2; }
    if (x[6] > bv) { bv = x[6]; g = 3; }
    g_gid[p] = (unsigned char)g;

    __syncthreads();
    // L0: 7 -> 64
#pragma unroll 1
    for (int c0 = 0; c0 < 64; c0 += 8) {
        float acc[8];
#pragma unroll
        for (int u = 0; u < 8; u++) {
            const float* wr = &wbuf[(c0 + u) * 7];
            float s = wbuf[448 + c0 + u];
#pragma unroll
            for (int k = 0; k < 7; k++) s = fmaf(wr[k], x[k], s);
            acc[u] = s;
        }
#pragma unroll
        for (int u = 0; u < 8; u++) hA[(c0 + u) * 128 + tid] = fmaxf(acc[u], 0.0f);
    }
    mlp64s(wbuf + 512, wbuf + 4608, hA, hB, tid);   // L1
    __syncthreads();                                // done reading w0/w1

    // phase 2: w2|b2
    smcpy128(wbuf + 0,    wl2, 4096, tid);
    smcpy128(wbuf + 4096, bl2, 64,   tid);
    __syncthreads();
    mlp64s(wbuf + 0, wbuf + 4096, hB, hA, tid);     // L2
    __syncthreads();                                // done reading w2

    // phase 3: w3|b3
    smcpy128(wbuf + 0,    wl3, 8192, tid);
    smcpy128(wbuf + 8192, bl3, 128,  tid);
    __syncthreads();

    float* op = g_h4 + (size_t)b * 128 * NPTS + i;
#pragma unroll 1
    for (int c0 = 0; c0 < 128; c0 += 8) {
        float acc[8];
#pragma unroll
        for (int u = 0; u < 8; u++) acc[u] = wbuf[8192 + c0 + u];
#pragma unroll 4
        for (int k = 0; k < 64; k += 4) {
            float a0 = hA[(k + 0) * 128 + tid];
            float a1 = hA[(k + 1) * 128 + tid];
            float a2 = hA[(k + 2) * 128 + tid];
            float a3 = hA[(k + 3) * 128 + tid];
#pragma unroll
            for (int u = 0; u < 8; u++) {
                float4 w4 = *reinterpret_cast<const float4*>(&wbuf[(c0 + u) * 64 + k]);
                acc[u] = fmaf(w4.x, a0, acc[u]);
                acc[u] = fmaf(w4.y, a1, acc[u]);
                acc[u] = fmaf(w4.z, a2, acc[u]);
                acc[u] = fmaf(w4.w, a3, acc[u]);
            }
        }
#pragma unroll
        for (int u = 0; u < 8; u++) op[(size_t)(c0 + u) * NPTS] = fmaxf(acc[u], 0.0f);
    }
}

// ---------------- kernel B: persistent 3-pass split-tf32 mma.sync + cp.async H pipeline ----------------
#define WS 132
#define HS 136
#define KB_W_FL (128 * WS)
#define KB_H_FL (128 * HS)
#define KB_SMEM_FLOATS (KB_W_FL + 2 * KB_H_FL)   // 51712 floats = 206848 B

__global__ __launch_bounds__(256, 1)
void kB(const float* __restrict__ wl4, const float* __restrict__ bl4) {
    extern __shared__ float sm[];
    float* sw = sm;
    float* hbuf0 = sm + KB_W_FL;
    float* hbuf1 = hbuf0 + KB_H_FL;
    __shared__ unsigned char gid_s[128];

    const int tid = threadIdx.x;
    const int bid = blockIdx.x;
    const int b  = bid >> 6;
    const int pg = (bid >> 3) & 7;
    const int cc = bid & 7;
    const int c0 = cc * 128;

    // W tile [c][k]
#pragma unroll
    for (int j = 0; j < 16; j++) {
        int idx = j * 256 + tid;
        int r = idx >> 5, q = (idx & 31) * 4;
        float4 v = *reinterpret_cast<const float4*>(wl4 + (size_t)(c0 + r) * 128 + q);
        *reinterpret_cast<float4*>(&sw[r * WS + q]) = v;
    }

    const u32 hadd[2] = { smem_u32(hbuf0), smem_u32(hbuf1) };
    // prefetch H tile 0
    {
        const int pbase = pg * 2048;
#pragma unroll
        for (int j = 0; j < 16; j++) {
            int idx = j * 256 + tid;
            int k = idx >> 5, q = (idx & 31) * 4;
            CP_ASYNC16(hadd[0] + (u32)(k * HS + q) * 4,
                       g_h4 + ((size_t)b * 128 + k) * NPTS + pbase + q);
        }
        CP_COMMIT();
    }

    const int lane = tid & 31, wrp = tid >> 5;
    const int mw = wrp >> 1;
    const int nw = wrp & 1;
    const int gid4 = lane >> 2, tig = lane & 3;
    const int cw = mw * 32, pw = nw * 64;

#pragma unroll 1
    for (int t = 0; t < 16; t++) {
        const int pbase = (pg * 16 + t) * 128;
        float* sh = (t & 1) ? hbuf1 : hbuf0;
        // prefetch next tile into other buffer, then wait for current
        if (t + 1 < 16) {
            const int pn = (pg * 16 + t + 1) * 128;
            const u32 dsta = hadd[(t + 1) & 1];
#pragma unroll
            for (int j = 0; j < 16; j++) {
                int idx = j * 256 + tid;
                int k = idx >> 5, q = (idx & 31) * 4;
                CP_ASYNC16(dsta + (u32)(k * HS + q) * 4,
                           g_h4 + ((size_t)b * 128 + k) * NPTS + pn + q);
            }
            CP_COMMIT();
            CP_WAIT1();
        } else {
            CP_WAIT0();
        }
        if (tid < 128) gid_s[tid] = g_gid[b * NPTS + pbase + tid];
        __syncthreads();

        float acc[2][8][4];
#pragma unroll
        for (int mt = 0; mt < 2; mt++)
#pragma unroll
            for (int nt = 0; nt < 8; nt++)
#pragma unroll
                for (int j = 0; j < 4; j++) acc[mt][nt][j] = 0.0f;

#pragma unroll 2
        for (int kk = 0; kk < 16; kk++) {
            const int kb = kk * 8;
            float ah[2][4], al[2][4];
#pragma unroll
            for (int mt = 0; mt < 2; mt++) {
                const int cb = cw + mt * 16;
                float x0 = sw[(cb + gid4) * WS + kb + tig];
                float x1 = sw[(cb + gid4 + 8) * WS + kb + tig];
                float x2 = sw[(cb + gid4) * WS + kb + tig + 4];
                float x3 = sw[(cb + gid4 + 8) * WS + kb + tig + 4];
                ah[mt][0] = cvt_tf32(x0); al[mt][0] = x0 - ah[mt][0];
                ah[mt][1] = cvt_tf32(x1); al[mt][1] = x1 - ah[mt][1];
                ah[mt][2] = cvt_tf32(x2); al[mt][2] = x2 - ah[mt][2];
                ah[mt][3] = cvt_tf32(x3); al[mt][3] = x3 - ah[mt][3];
            }
            float bh[8][2], bl[8][2];
#pragma unroll
            for (int nt = 0; nt < 8; nt++) {
                const int pp = pw + nt * 8 + gid4;
                float y0 = sh[(kb + tig) * HS + pp];
                float y1 = sh[(kb + tig + 4) * HS + pp];
                bh[nt][0] = cvt_tf32(y0); bl[nt][0] = y0 - bh[nt][0];
                bh[nt][1] = cvt_tf32(y1); bl[nt][1] = y1 - bh[nt][1];
            }
#pragma unroll
            for (int mt = 0; mt < 2; mt++)
#pragma unroll
                for (int nt = 0; nt < 8; nt++) {
                    mma8(acc[mt][nt], ah[mt], bh[nt]);
                    mma8(acc[mt][nt], ah[mt], bl[nt]);
                    mma8(acc[mt][nt], al[mt], bh[nt]);
                }
        }
        __syncthreads();   // all reads of sh done; reuse sh region for staging

        u64* skey = reinterpret_cast<u64*>(sh);              // 8 KB
        float* sg = reinterpret_cast<float*>(skey + 1024);   // 16 KB
        const int slot = nw * 4 + tig;
#pragma unroll
        for (int mt = 0; mt < 2; mt++)
#pragma unroll
            for (int hf = 0; hf < 2; hf++) {
                const int c = cw + mt * 16 + gid4 + hf * 8;
                const float bias_c = __ldg(&bl4[c0 + c]);
                u64 key = 0ull;
                float g0 = 0.f, g1 = 0.f, g2 = 0.f, g3 = 0.f;
#pragma unroll
                for (int nt = 0; nt < 8; nt++)
#pragma unroll
                    for (int jj = 0; jj < 2; jj++) {
                        float val = fmaxf(acc[mt][nt][hf * 2 + jj] + bias_c, 0.0f);
                        const int pl = pw + nt * 8 + tig * 2 + jj;
                        u64 k = ((u64)__float_as_uint(val) << 32) |
                                (u64)(0xFFFFFFFFu - (u32)(pbase + pl));
                        if (k > key) key = k;
                        const int gi = gid_s[pl];
                        g0 = fmaxf(g0, gi == 0 ? val : 0.f);
                        g1 = fmaxf(g1, gi == 1 ? val : 0.f);
                        g2 = fmaxf(g2, gi == 2 ? val : 0.f);
                        g3 = fmaxf(g3, gi == 3 ? val : 0.f);
                    }
                skey[c * 8 + slot] = key;
                sg[(c * 8 + slot) * 4 + 0] = g0;
                sg[(c * 8 + slot) * 4 + 1] = g1;
                sg[(c * 8 + slot) * 4 + 2] = g2;
                sg[(c * 8 + slot) * 4 + 3] = g3;
            }
        __syncthreads();

        if (tid < 128) {
            const int c = tid;
            u64 m = skey[c * 8];
            float mg[4] = { sg[c * 32 + 0], sg[c * 32 + 1], sg[c * 32 + 2], sg[c * 32 + 3] };
#pragma unroll
            for (int q = 1; q < 8; q++) {
                u64 e = skey[c * 8 + q];
                if (e > m) m = e;
#pragma unroll
                for (int g = 0; g < 4; g++) mg[g] = fmaxf(mg[g], sg[(c * 8 + q) * 4 + g]);
            }
            atomicMax(&g_pmax[b * 1024 + c0 + c], m);
#pragma unroll
            for (int g = 0; g < 4; g++)
                atomicMax(&g_gmax[g * 1024 + c0 + c], __float_as_uint(mg[g]));
        }
        __syncthreads();   // staging reads done before this buffer is prefetch-overwritten
    }
}

// ---------------- init + tail MLPs (unchanged) ----------------
__global__ void kInit() {
    int t = blockIdx.x * blockDim.x + threadIdx.x;
    if (t < BATCH * 1024) g_pmax[t] = 0ull;
    if (t < 4 * 1024) g_gmax[t] = 0u;
}

__global__ void kC1(const float* __restrict__ wg0, const float* __restrict__ bg0,
                    const float* __restrict__ wgr0, const float* __restrict__ bgr0,
                    float* __restrict__ out) {
    const int gtid = blockIdx.x * blockDim.x + threadIdx.x;
    if (gtid < BATCH * 1024) {
        unsigned long long pv = g_pmax[gtid];
        out[4096 + gtid] = (float)(0xFFFFFFFFu - (unsigned int)(pv & 0xFFFFFFFFull));
    }
    const int wid = gtid >> 5;
    const int lane = gtid & 31;
    const int row = wid >> 9;
    const int j = wid & 511;
    if (row > 16) return;
    float s = 0.0f;
    if (row < 16) {
        const float* wr = wg0 + (size_t)j * 1024;
        const unsigned long long* pbuf = g_pmax + row * 1024;
        for (int k = lane; k < 1024; k += 32)
            s = fmaf(wr[k], __uint_as_float((unsigned int)(pbuf[k] >> 32)), s);
    } else {
        const float* wr = wgr0 + (size_t)j * 4096;
        for (int k = lane; k < 4096; k += 32)
            s = fmaf(wr[k], __uint_as_float(g_gmax[k]), s);
    }
#pragma unroll
    for (int o = 16; o; o >>= 1) s += __shfl_xor_sync(0xFFFFFFFFu, s, o);
    if (lane == 0) {
        float bb = (row < 16) ? bg0[j] : bgr0[j];
        g_u1[row * 512 + j] = fmaxf(s + bb, 0.0f);
    }
}

__global__ void kC2(const float* __restrict__ wg1, const float* __restrict__ bg1,
                    const float* __restrict__ wgr1, const float* __restrict__ bgr1,
                    float* __restrict__ out) {
    const int gtid = blockIdx.x * blockDim.x + threadIdx.x;
    const int wid = gtid >> 5;
    const int lane = gtid & 31;
    const int row = wid >> 7;
    const int j = wid & 127;
    if (row > 16) return;
    const float* wr = ((row < 16) ? wg1 : wgr1) + (size_t)j * 512;
    const float* in = g_u1 + row * 512;
    float s = 0.0f;
    for (int k = lane; k < 512; k += 32) s = fmaf(wr[k], in[k], s);
#pragma unroll
    for (int o = 16; o; o >>= 1) s += __shfl_xor_sync(0xFFFFFFFFu, s, o);
    s = __shfl_sync(0xFFFFFFFFu, s, 0);
    float bb = (row < 16) ? bg1[j] : bgr1[j];
    float val = fmaxf(s + bb, 0.0f);
    if (row < 16) {
        if (lane == 0) out[row * 256 + 128 + j] = val;
    } else {
        if (lane < 16) out[lane * 256 + j] = val;
    }
}

// ---------------- launch ----------------
extern "C" void kernel_launch(void* const* d_in, const int* in_sizes, int n_in,
                              void* d_out, int out_size) {
    const float* points = (const float*)d_in[0];
    const float* wl0 = (const float*)d_in[1];  const float* bl0 = (const float*)d_in[2];
    const float* wl1 = (const float*)d_in[3];  const float* bl1 = (const float*)d_in[4];
    const float* wl2 = (const float*)d_in[5];  const float* bl2 = (const float*)d_in[6];
    const float* wl3 = (const float*)d_in[7];  const float* bl3 = (const float*)d_in[8];
    const float* wl4 = (const float*)d_in[9];  const float* bl4 = (const float*)d_in[10];
    const float* wg0 = (const float*)d_in[11]; const float* bg0 = (const float*)d_in[12];
    const float* wg1 = (const float*)d_in[13]; const float* bg1 = (const float*)d_in[14];
    const float* wgr0 = (const float*)d_in[15]; const float* bgr0 = (const float*)d_in[16];
    const float* wgr1 = (const float*)d_in[17]; const float* bgr1 = (const float*)d_in[18];
    float* out = (float*)d_out;

    cudaFuncSetAttribute(kA, cudaFuncAttributeMaxDynamicSharedMemorySize,
                         KA_SMEM_FLOATS * (int)sizeof(float));
    cudaFuncSetAttribute(kB, cudaFuncAttributeMaxDynamicSharedMemorySize,
                         KB_SMEM_FLOATS * (int)sizeof(float));

    kInit<<<64, 256>>>();
    kA<<<(BATCH * NPTS) / 128, 128, KA_SMEM_FLOATS * sizeof(float)>>>(
        points, wl0, bl0, wl1, bl1, wl2, bl2, wl3, bl3);
    kB<<<1024, 256, KB_SMEM_FLOATS * sizeof(float)>>>(wl4, bl4);
    kC1<<<1088, 256>>>(wg0, bg0, wgr0, bgr0, out);
    kC2<<<272, 256>>>(wg1, bg1, wgr1, bgr1, out);
}

// round 8
// speedup vs baseline: 1.7624x; 1.2542x over previous
#include <cuda_runtime.h>
#include <cuda_fp16.h>
#include <cstdint>

#define NPTS 16384
#define BATCH 16
#define INC 7
typedef unsigned long long u64;
typedef unsigned int u32;

// ---------------- scratch ----------------
__device__ u32                g_hp[(size_t)BATCH * 128 * NPTS]; // (b, k, i) packed (hi16|lo16)
__device__ u32                g_wp[1024 * 128];                 // (c, k) packed limbs of 64*W
__device__ unsigned char      g_gid[BATCH * NPTS];
__device__ unsigned long long g_pmax[BATCH * 1024];  // (valbits<<32)|(~idx)
__device__ unsigned int       g_gmax[4 * 1024];
__device__ float              g_u1[17 * 512];

__device__ __forceinline__ u32 pack_limbs(float v) {
    __half hi = __float2half_rn(v);
    float r = v - __half2float(hi);
    __half lo = __float2half_rn(r);
    return (u32)__half_as_ushort(hi) | ((u32)__half_as_ushort(lo) << 16);
}
__device__ __forceinline__ void mma16(float* d, const u32* a, const u32* b) {
    asm volatile("mma.sync.aligned.m16n8k16.row.col.f32.f16.f16.f32 "
                 "{%0,%1,%2,%3}, {%4,%5,%6,%7}, {%8,%9}, {%0,%1,%2,%3};"
                 : "+f"(d[0]), "+f"(d[1]), "+f"(d[2]), "+f"(d[3])
                 : "r"(a[0]), "r"(a[1]), "r"(a[2]), "r"(a[3]), "r"(b[0]), "r"(b[1]));
}
__device__ __forceinline__ u32 smem_u32(const void* p) {
    u32 a; asm("{ .reg .u64 t; cvta.to.shared.u64 t, %1; cvt.u32.u64 %0, t; }" : "=r"(a) : "l"(p)); return a;
}
#define CP_ASYNC16(dst, src) asm volatile("cp.async.cg.shared.global [%0], [%1], 16;" :: "r"(dst), "l"(src) : "memory")
#define CP_COMMIT()  asm volatile("cp.async.commit_group;" ::: "memory")
#define CP_WAIT0()   asm volatile("cp.async.wait_group 0;" ::: "memory")
#define CP_WAIT1()   asm volatile("cp.async.wait_group 1;" ::: "memory")

// ---------------- kernel A: fused 7->64->64->64->128 (R7 proven) + limb-packed output ----------------
#define KA_SMEM_FLOATS 24704

__device__ __forceinline__ void smcpy128(float* dst, const float* src, int n, int tid) {
    for (int i = tid; i < n; i += 128) dst[i] = src[i];
}
__device__ __forceinline__ void mlp64s(const float* __restrict__ sw, const float* __restrict__ sb,
                                       const float* __restrict__ ain, float* __restrict__ aout, int tid) {
#pragma unroll 1
    for (int c0 = 0; c0 < 64; c0 += 8) {
        float acc[8];
#pragma unroll
        for (int u = 0; u < 8; u++) acc[u] = sb[c0 + u];
#pragma unroll 4
        for (int k = 0; k < 64; k += 4) {
            float a0 = ain[(k + 0) * 128 + tid];
            float a1 = ain[(k + 1) * 128 + tid];
            float a2 = ain[(k + 2) * 128 + tid];
            float a3 = ain[(k + 3) * 128 + tid];
#pragma unroll
            for (int u = 0; u < 8; u++) {
                float4 w4 = *reinterpret_cast<const float4*>(&sw[(c0 + u) * 64 + k]);
                acc[u] = fmaf(w4.x, a0, acc[u]);
                acc[u] = fmaf(w4.y, a1, acc[u]);
                acc[u] = fmaf(w4.z, a2, acc[u]);
                acc[u] = fmaf(w4.w, a3, acc[u]);
            }
        }
#pragma unroll
        for (int u = 0; u < 8; u++) aout[(c0 + u) * 128 + tid] = fmaxf(acc[u], 0.0f);
    }
}

__global__ __launch_bounds__(128, 2)
void kA(const float* __restrict__ points,
        const float* __restrict__ wl0, const float* __restrict__ bl0,
        const float* __restrict__ wl1, const float* __restrict__ bl1,
        const float* __restrict__ wl2, const float* __restrict__ bl2,
        const float* __restrict__ wl3, const float* __restrict__ bl3) {
    extern __shared__ float sm[];
    float* wbuf = sm;
    float* hA = sm + 8320;
    float* hB = sm + 16512;
    const int tid = threadIdx.x;

    smcpy128(wbuf + 0,    wl0, 448,  tid);
    smcpy128(wbuf + 448,  bl0, 64,   tid);
    smcpy128(wbuf + 512,  wl1, 4096, tid);
    smcpy128(wbuf + 4608, bl1, 64,   tid);

    const int p = blockIdx.x * 128 + tid;
    const int b = p >> 14;
    const int i = p & (NPTS - 1);
    const float* pt = points + (size_t)b * INC * NPTS + i;
    float x[INC];
#pragma unroll
    for (int c = 0; c < INC; c++) x[c] = pt[(size_t)c * NPTS];

    int g = 0; float bv = x[3];
    if (x[4] > bv) { bv = x[4]; g = 1; }
    if (x[5] > bv) { bv = x[5]; g = 2; }
    if (x[6] > bv) { bv = x[6]; g = 3; }
    g_gid[p] = (unsigned char)g;

    __syncthreads();
#pragma unroll 1
    for (int c0 = 0; c0 < 64; c0 += 8) {
        float acc[8];
#pragma unroll
        for (int u = 0; u < 8; u++) {
            const float* wr = &wbuf[(c0 + u) * 7];
            float s = wbuf[448 + c0 + u];
#pragma unroll
            for (int k = 0; k < 7; k++) s = fmaf(wr[k], x[k], s);
            acc[u] = s;
        }
#pragma unroll
        for (int u = 0; u < 8; u++) hA[(c0 + u) * 128 + tid] = fmaxf(acc[u], 0.0f);
    }
    mlp64s(wbuf + 512, wbuf + 4608, hA, hB, tid);   // L1
    __syncthreads();

    smcpy128(wbuf + 0,    wl2, 4096, tid);
    smcpy128(wbuf + 4096, bl2, 64,   tid);
    __syncthreads();
    mlp64s(wbuf + 0, wbuf + 4096, hB, hA, tid);     // L2
    __syncthreads();

    smcpy128(wbuf + 0,    wl3, 8192, tid);
    smcpy128(wbuf + 8192, bl3, 128,  tid);
    __syncthreads();

    u32* op = g_hp + (size_t)b * 128 * NPTS + i;
#pragma unroll 1
    for (int c0 = 0; c0 < 128; c0 += 8) {
        float acc[8];
#pragma unroll
        for (int u = 0; u < 8; u++) acc[u] = wbuf[8192 + c0 + u];
#pragma unroll 4
        for (int k = 0; k < 64; k += 4) {
            float a0 = hA[(k + 0) * 128 + tid];
            float a1 = hA[(k + 1) * 128 + tid];
            float a2 = hA[(k + 2) * 128 + tid];
            float a3 = hA[(k + 3) * 128 + tid];
#pragma unroll
            for (int u = 0; u < 8; u++) {
                float4 w4 = *reinterpret_cast<const float4*>(&wbuf[(c0 + u) * 64 + k]);
                acc[u] = fmaf(w4.x, a0, acc[u]);
                acc[u] = fmaf(w4.y, a1, acc[u]);
                acc[u] = fmaf(w4.z, a2, acc[u]);
                acc[u] = fmaf(w4.w, a3, acc[u]);
            }
        }
#pragma unroll
        for (int u = 0; u < 8; u++)
            op[(size_t)(c0 + u) * NPTS] = pack_limbs(fmaxf(acc[u], 0.0f));
    }
}

// ---------------- kernel W: split 64*W into fp16 limbs ----------------
__global__ void kW(const float* __restrict__ wl4) {
    int t = blockIdx.x * blockDim.x + threadIdx.x;
    if (t >= 1024 * 128) return;
    g_wp[t] = pack_limbs(wl4[t] * 64.0f);
}

// ---------------- kernel B: persistent 3-pass split-fp16 mma.sync m16n8k16 ----------------
#define WSU 132
#define HSU 132
#define KB_W_U (128 * WSU)
#define KB_H_U (128 * HSU)
#define KB_SMEM_BYTES ((KB_W_U + 2 * KB_H_U) * 4)   // 202752 B

__global__ __launch_bounds__(256, 1)
void kB(const float* __restrict__ bl4) {
    extern __shared__ float smf[];
    u32* swu = reinterpret_cast<u32*>(smf);
    u32* hbuf0 = swu + KB_W_U;
    u32* hbuf1 = hbuf0 + KB_H_U;
    __shared__ unsigned char gid_s[128];

    const int tid = threadIdx.x;
    const int bid = blockIdx.x;
    const int b  = bid >> 6;
    const int pg = (bid >> 3) & 7;
    const int cc = bid & 7;
    const int c0 = cc * 128;

    // W tile [c][k] packed u32
#pragma unroll
    for (int j = 0; j < 16; j++) {
        int idx = j * 256 + tid;
        int r = idx >> 5, q = (idx & 31) * 4;
        uint4 v = *reinterpret_cast<const uint4*>(g_wp + (size_t)(c0 + r) * 128 + q);
        *reinterpret_cast<uint4*>(&swu[r * WSU + q]) = v;
    }

    const u32 hadd[2] = { smem_u32(hbuf0), smem_u32(hbuf1) };
    {
        const int pbase = pg * 2048;
#pragma unroll
        for (int j = 0; j < 16; j++) {
            int idx = j * 256 + tid;
            int k = idx >> 5, q = (idx & 31) * 4;
            CP_ASYNC16(hadd[0] + (u32)(k * HSU + q) * 4,
                       g_hp + ((size_t)b * 128 + k) * NPTS + pbase + q);
        }
        CP_COMMIT();
    }

    const int lane = tid & 31, wrp = tid >> 5;
    const int mw = wrp >> 1;
    const int nw = wrp & 1;
    const int gid4 = lane >> 2, tig = lane & 3;
    const int cw = mw * 32, pw = nw * 64;

#pragma unroll 1
    for (int t = 0; t < 16; t++) {
        const int pbase = (pg * 16 + t) * 128;
        u32* shu = (t & 1) ? hbuf1 : hbuf0;
        if (t + 1 < 16) {
            const int pn = (pg * 16 + t + 1) * 128;
            const u32 dsta = hadd[(t + 1) & 1];
#pragma unroll
            for (int j = 0; j < 16; j++) {
                int idx = j * 256 + tid;
                int k = idx >> 5, q = (idx & 31) * 4;
                CP_ASYNC16(dsta + (u32)(k * HSU + q) * 4,
                           g_hp + ((size_t)b * 128 + k) * NPTS + pn + q);
            }
            CP_COMMIT();
            CP_WAIT1();
        } else {
            CP_WAIT0();
        }
        if (tid < 128) gid_s[tid] = g_gid[b * NPTS + pbase + tid];
        __syncthreads();

        float acc[2][8][4];
#pragma unroll
        for (int mt = 0; mt < 2; mt++)
#pragma unroll
            for (int nt = 0; nt < 8; nt++)
#pragma unroll
                for (int j = 0; j < 4; j++) acc[mt][nt][j] = 0.0f;

#pragma unroll 1
        for (int kk = 0; kk < 8; kk++) {
            const int kb = kk * 16;
            u32 ahi[2][4], alo[2][4];
#pragma unroll
            for (int mt = 0; mt < 2; mt++) {
                const int r0 = cw + mt * 16 + gid4;
                const int kc = kb + tig * 2;
#pragma unroll
                for (int q = 0; q < 4; q++) {
                    const int rr = r0 + (q & 1) * 8;
                    const int kq = kc + (q >> 1) * 8;
                    u64 v = *reinterpret_cast<const u64*>(&swu[rr * WSU + kq]);
                    u32 v0 = (u32)v, v1 = (u32)(v >> 32);
                    ahi[mt][q] = __byte_perm(v0, v1, 0x5410);
                    alo[mt][q] = __byte_perm(v0, v1, 0x7632);
                }
            }
            u32 bhi[8][2], blo[8][2];
            const int krow = kb + tig * 2;
#pragma unroll
            for (int nt = 0; nt < 8; nt++) {
                const int pp = pw + nt * 8 + gid4;
#pragma unroll
                for (int q = 0; q < 2; q++) {
                    const int kr = krow + q * 8;
                    u32 v0 = shu[kr * HSU + pp];
                    u32 v1 = shu[(kr + 1) * HSU + pp];
                    bhi[nt][q] = __byte_perm(v0, v1, 0x5410);
                    blo[nt][q] = __byte_perm(v0, v1, 0x7632);
                }
            }
#pragma unroll
            for (int mt = 0; mt < 2; mt++)
#pragma unroll
                for (int nt = 0; nt < 8; nt++) {
                    mma16(acc[mt][nt], ahi[mt], bhi[nt]);
                    mma16(acc[mt][nt], ahi[mt], blo[nt]);
                    mma16(acc[mt][nt], alo[mt], bhi[nt]);
                }
        }
        __syncthreads();   // all reads of shu done; reuse region for staging

        u64* skey = reinterpret_cast<u64*>(shu);             // 8 KB
        float* sg = reinterpret_cast<float*>(skey + 1024);   // 16 KB
        const int slot = nw * 4 + tig;
#pragma unroll
        for (int mt = 0; mt < 2; mt++)
#pragma unroll
            for (int hf = 0; hf < 2; hf++) {
                const int c = cw + mt * 16 + gid4 + hf * 8;
                const float bias_c = __ldg(&bl4[c0 + c]);
                u64 key = 0ull;
                float g0 = 0.f, g1 = 0.f, g2 = 0.f, g3 = 0.f;
#pragma unroll
                for (int nt = 0; nt < 8; nt++)
#pragma unroll
                    for (int jj = 0; jj < 2; jj++) {
                        float val = fmaxf(fmaf(acc[mt][nt][hf * 2 + jj], 0.015625f, bias_c), 0.0f);
                        const int pl = pw + nt * 8 + tig * 2 + jj;
                        u64 k = ((u64)__float_as_uint(val) << 32) |
                                (u64)(0xFFFFFFFFu - (u32)(pbase + pl));
                        if (k > key) key = k;
                        const int gi = gid_s[pl];
                        g0 = fmaxf(g0, gi == 0 ? val : 0.f);
                        g1 = fmaxf(g1, gi == 1 ? val : 0.f);
                        g2 = fmaxf(g2, gi == 2 ? val : 0.f);
                        g3 = fmaxf(g3, gi == 3 ? val : 0.f);
                    }
                skey[c * 8 + slot] = key;
                sg[(c * 8 + slot) * 4 + 0] = g0;
                sg[(c * 8 + slot) * 4 + 1] = g1;
                sg[(c * 8 + slot) * 4 + 2] = g2;
                sg[(c * 8 + slot) * 4 + 3] = g3;
            }
        __syncthreads();

        if (tid < 128) {
            const int c = tid;
            u64 m = skey[c * 8];
            float mg[4] = { sg[c * 32 + 0], sg[c * 32 + 1], sg[c * 32 + 2], sg[c * 32 + 3] };
#pragma unroll
            for (int q = 1; q < 8; q++) {
                u64 e = skey[c * 8 + q];
                if (e > m) m = e;
#pragma unroll
                for (int g = 0; g < 4; g++) mg[g] = fmaxf(mg[g], sg[(c * 8 + q) * 4 + g]);
            }
            atomicMax(&g_pmax[b * 1024 + c0 + c], m);
#pragma unroll
            for (int g = 0; g < 4; g++)
                atomicMax(&g_gmax[g * 1024 + c0 + c], __float_as_uint(mg[g]));
        }
        __syncthreads();   // staging reads done before buffer is prefetch-overwritten
    }
}

// ---------------- init + tail MLPs (unchanged) ----------------
__global__ void kInit() {
    int t = blockIdx.x * blockDim.x + threadIdx.x;
    if (t < BATCH * 1024) g_pmax[t] = 0ull;
    if (t < 4 * 1024) g_gmax[t] = 0u;
}

__global__ void kC1(const float* __restrict__ wg0, const float* __restrict__ bg0,
                    const float* __restrict__ wgr0, const float* __restrict__ bgr0,
                    float* __restrict__ out) {
    const int gtid = blockIdx.x * blockDim.x + threadIdx.x;
    if (gtid < BATCH * 1024) {
        unsigned long long pv = g_pmax[gtid];
        out[4096 + gtid] = (float)(0xFFFFFFFFu - (unsigned int)(pv & 0xFFFFFFFFull));
    }
    const int wid = gtid >> 5;
    const int lane = gtid & 31;
    const int row = wid >> 9;
    const int j = wid & 511;
    if (row > 16) return;
    float s = 0.0f;
    if (row < 16) {
        const float* wr = wg0 + (size_t)j * 1024;
        const unsigned long long* pbuf = g_pmax + row * 1024;
        for (int k = lane; k < 1024; k += 32)
            s = fmaf(wr[k], __uint_as_float((unsigned int)(pbuf[k] >> 32)), s);
    } else {
        const float* wr = wgr0 + (size_t)j * 4096;
        for (int k = lane; k < 4096; k += 32)
            s = fmaf(wr[k], __uint_as_float(g_gmax[k]), s);
    }
#pragma unroll
    for (int o = 16; o; o >>= 1) s += __shfl_xor_sync(0xFFFFFFFFu, s, o);
    if (lane == 0) {
        float bb = (row < 16) ? bg0[j] : bgr0[j];
        g_u1[row * 512 + j] = fmaxf(s + bb, 0.0f);
    }
}

__global__ void kC2(const float* __restrict__ wg1, const float* __restrict__ bg1,
                    const float* __restrict__ wgr1, const float* __restrict__ bgr1,
                    float* __restrict__ out) {
    const int gtid = blockIdx.x * blockDim.x + threadIdx.x;
    const int wid = gtid >> 5;
    const int lane = gtid & 31;
    const int row = wid >> 7;
    const int j = wid & 127;
    if (row > 16) return;
    const float* wr = ((row < 16) ? wg1 : wgr1) + (size_t)j * 512;
    const float* in = g_u1 + row * 512;
    float s = 0.0f;
    for (int k = lane; k < 512; k += 32) s = fmaf(wr[k], in[k], s);
#pragma unroll
    for (int o = 16; o; o >>= 1) s += __shfl_xor_sync(0xFFFFFFFFu, s, o);
    s = __shfl_sync(0xFFFFFFFFu, s, 0);
    float bb = (row < 16) ? bg1[j] : bgr1[j];
    float val = fmaxf(s + bb, 0.0f);
    if (row < 16) {
        if (lane == 0) out[row * 256 + 128 + j] = val;
    } else {
        if (lane < 16) out[lane * 256 + j] = val;
    }
}

// ---------------- launch ----------------
extern "C" void kernel_launch(void* const* d_in, const int* in_sizes, int n_in,
                              void* d_out, int out_size) {
    const float* points = (const float*)d_in[0];
    const float* wl0 = (const float*)d_in[1];  const float* bl0 = (const float*)d_in[2];
    const float* wl1 = (const float*)d_in[3];  const float* bl1 = (const float*)d_in[4];
    const float* wl2 = (const float*)d_in[5];  const float* bl2 = (const float*)d_in[6];
    const float* wl3 = (const float*)d_in[7];  const float* bl3 = (const float*)d_in[8];
    const float* wl4 = (const float*)d_in[9];  const float* bl4 = (const float*)d_in[10];
    const float* wg0 = (const float*)d_in[11]; const float* bg0 = (const float*)d_in[12];
    const float* wg1 = (const float*)d_in[13]; const float* bg1 = (const float*)d_in[14];
    const float* wgr0 = (const float*)d_in[15]; const float* bgr0 = (const float*)d_in[16];
    const float* wgr1 = (const float*)d_in[17]; const float* bgr1 = (const float*)d_in[18];
    float* out = (float*)d_out;

    cudaFuncSetAttribute(kA, cudaFuncAttributeMaxDynamicSharedMemorySize,
                         KA_SMEM_FLOATS * (int)sizeof(float));
    cudaFuncSetAttribute(kB, cudaFuncAttributeMaxDynamicSharedMemorySize, KB_SMEM_BYTES);

    kInit<<<64, 256>>>();
    kW<<<512, 256>>>(wl4);
    kA<<<(BATCH * NPTS) / 128, 128, KA_SMEM_FLOATS * sizeof(float)>>>(
        points, wl0, bl0, wl1, bl1, wl2, bl2, wl3, bl3);
    kB<<<1024, 256, KB_SMEM_BYTES>>>(bl4);
    kC1<<<1088, 256>>>(wg0, bg0, wgr0, bgr0, out);
    kC2<<<272, 256>>>(wg1, bg1, wgr1, bgr1, out);
}

// round 9
// speedup vs baseline: 1.8575x; 1.0540x over previous
#include <cuda_runtime.h>
#include <cuda_fp16.h>
#include <cstdint>

#define NPTS 16384
#define BATCH 16
#define INC 7
typedef unsigned long long u64;
typedef unsigned int u32;

// ---------------- scratch ----------------
// plane-separated, k-pair packed: u32 = half2(val[2kp], val[2kp+1])
__device__ u32                g_hhi[(size_t)BATCH * 64 * NPTS]; // (b, kp, i)
__device__ u32                g_hlo[(size_t)BATCH * 64 * NPTS];
__device__ u32                g_wphi[1024 * 64];                // (c, kp) of 64*W
__device__ u32                g_wplo[1024 * 64];
__device__ unsigned char      g_gid[BATCH * NPTS];
__device__ unsigned long long g_pmax[BATCH * 1024];  // (valbits<<32)|(~idx)
__device__ unsigned int       g_gmax[4 * 1024];
__device__ float              g_u1[17 * 512];

__device__ __forceinline__ void split_limbs(float v, unsigned short& hi, unsigned short& lo) {
    __half h = __float2half_rn(v);
    float r = v - __half2float(h);
    __half l = __float2half_rn(r);
    hi = __half_as_ushort(h);
    lo = __half_as_ushort(l);
}
__device__ __forceinline__ void mma16(float* d, const u32* a, const u32* b) {
    asm volatile("mma.sync.aligned.m16n8k16.row.col.f32.f16.f16.f32 "
                 "{%0,%1,%2,%3}, {%4,%5,%6,%7}, {%8,%9}, {%0,%1,%2,%3};"
                 : "+f"(d[0]), "+f"(d[1]), "+f"(d[2]), "+f"(d[3])
                 : "r"(a[0]), "r"(a[1]), "r"(a[2]), "r"(a[3]), "r"(b[0]), "r"(b[1]));
}
__device__ __forceinline__ u32 smem_u32(const void* p) {
    u32 a; asm("{ .reg .u64 t; cvta.to.shared.u64 t, %1; cvt.u32.u64 %0, t; }" : "=r"(a) : "l"(p)); return a;
}
#define CP_ASYNC16(dst, src) asm volatile("cp.async.cg.shared.global [%0], [%1], 16;" :: "r"(dst), "l"(src) : "memory")
#define CP_COMMIT()  asm volatile("cp.async.commit_group;" ::: "memory")
#define CP_WAIT0()   asm volatile("cp.async.wait_group 0;" ::: "memory")
#define CP_WAIT1()   asm volatile("cp.async.wait_group 1;" ::: "memory")

// ---------------- kernel A: fused 7->64->64->64->128 + plane-split output ----------------
#define KA_SMEM_FLOATS 24704

__device__ __forceinline__ void smcpy128(float* dst, const float* src, int n, int tid) {
    for (int i = tid; i < n; i += 128) dst[i] = src[i];
}
__device__ __forceinline__ void mlp64s(const float* __restrict__ sw, const float* __restrict__ sb,
                                       const float* __restrict__ ain, float* __restrict__ aout, int tid) {
#pragma unroll 1
    for (int c0 = 0; c0 < 64; c0 += 8) {
        float acc[8];
#pragma unroll
        for (int u = 0; u < 8; u++) acc[u] = sb[c0 + u];
#pragma unroll 4
        for (int k = 0; k < 64; k += 4) {
            float a0 = ain[(k + 0) * 128 + tid];
            float a1 = ain[(k + 1) * 128 + tid];
            float a2 = ain[(k + 2) * 128 + tid];
            float a3 = ain[(k + 3) * 128 + tid];
#pragma unroll
            for (int u = 0; u < 8; u++) {
                float4 w4 = *reinterpret_cast<const float4*>(&sw[(c0 + u) * 64 + k]);
                acc[u] = fmaf(w4.x, a0, acc[u]);
                acc[u] = fmaf(w4.y, a1, acc[u]);
                acc[u] = fmaf(w4.z, a2, acc[u]);
                acc[u] = fmaf(w4.w, a3, acc[u]);
            }
        }
#pragma unroll
        for (int u = 0; u < 8; u++) aout[(c0 + u) * 128 + tid] = fmaxf(acc[u], 0.0f);
    }
}

__global__ __launch_bounds__(128, 2)
void kA(const float* __restrict__ points,
        const float* __restrict__ wl0, const float* __restrict__ bl0,
        const float* __restrict__ wl1, const float* __restrict__ bl1,
        const float* __restrict__ wl2, const float* __restrict__ bl2,
        const float* __restrict__ wl3, const float* __restrict__ bl3) {
    extern __shared__ float sm[];
    float* wbuf = sm;
    float* hA = sm + 8320;
    float* hB = sm + 16512;
    const int tid = threadIdx.x;

    smcpy128(wbuf + 0,    wl0, 448,  tid);
    smcpy128(wbuf + 448,  bl0, 64,   tid);
    smcpy128(wbuf + 512,  wl1, 4096, tid);
    smcpy128(wbuf + 4608, bl1, 64,   tid);

    const int p = blockIdx.x * 128 + tid;
    const int b = p >> 14;
    const int i = p & (NPTS - 1);
    const float* pt = points + (size_t)b * INC * NPTS + i;
    float x[INC];
#pragma unroll
    for (int c = 0; c < INC; c++) x[c] = pt[(size_t)c * NPTS];

    int g = 0; float bv = x[3];
    if (x[4] > bv) { bv = x[4]; g = 1; }
    if (x[5] > bv) { bv = x[5]; g = 2; }
    if (x[6] > bv) { bv = x[6]; g = 3; }
    g_gid[p] = (unsigned char)g;

    __syncthreads();
#pragma unroll 1
    for (int c0 = 0; c0 < 64; c0 += 8) {
        float acc[8];
#pragma unroll
        for (int u = 0; u < 8; u++) {
            const float* wr = &wbuf[(c0 + u) * 7];
            float s = wbuf[448 + c0 + u];
#pragma unroll
            for (int k = 0; k < 7; k++) s = fmaf(wr[k], x[k], s);
            acc[u] = s;
        }
#pragma unroll
        for (int u = 0; u < 8; u++) hA[(c0 + u) * 128 + tid] = fmaxf(acc[u], 0.0f);
    }
    mlp64s(wbuf + 512, wbuf + 4608, hA, hB, tid);   // L1
    __syncthreads();

    smcpy128(wbuf + 0,    wl2, 4096, tid);
    smcpy128(wbuf + 4096, bl2, 64,   tid);
    __syncthreads();
    mlp64s(wbuf + 0, wbuf + 4096, hB, hA, tid);     // L2
    __syncthreads();

    smcpy128(wbuf + 0,    wl3, 8192, tid);
    smcpy128(wbuf + 8192, bl3, 128,  tid);
    __syncthreads();

    u32* ophi = g_hhi + (size_t)b * 64 * NPTS + i;
    u32* oplo = g_hlo + (size_t)b * 64 * NPTS + i;
#pragma unroll 1
    for (int c0 = 0; c0 < 128; c0 += 8) {
        float acc[8];
#pragma unroll
        for (int u = 0; u < 8; u++) acc[u] = wbuf[8192 + c0 + u];
#pragma unroll 4
        for (int k = 0; k < 64; k += 4) {
            float a0 = hA[(k + 0) * 128 + tid];
            float a1 = hA[(k + 1) * 128 + tid];
            float a2 = hA[(k + 2) * 128 + tid];
            float a3 = hA[(k + 3) * 128 + tid];
#pragma unroll
            for (int u = 0; u < 8; u++) {
                float4 w4 = *reinterpret_cast<const float4*>(&wbuf[(c0 + u) * 64 + k]);
                acc[u] = fmaf(w4.x, a0, acc[u]);
                acc[u] = fmaf(w4.y, a1, acc[u]);
                acc[u] = fmaf(w4.z, a2, acc[u]);
                acc[u] = fmaf(w4.w, a3, acc[u]);
            }
        }
#pragma unroll
        for (int j = 0; j < 4; j++) {
            unsigned short h0, l0, h1, l1;
            split_limbs(fmaxf(acc[2 * j], 0.0f), h0, l0);
            split_limbs(fmaxf(acc[2 * j + 1], 0.0f), h1, l1);
            const size_t kp = (size_t)(c0 / 2 + j) * NPTS;
            ophi[kp] = (u32)h0 | ((u32)h1 << 16);
            oplo[kp] = (u32)l0 | ((u32)l1 << 16);
        }
    }
}

// ---------------- kernel W: split 64*W into fp16 limb planes, k-pair packed ----------------
__global__ void kW(const float* __restrict__ wl4) {
    int t = blockIdx.x * blockDim.x + threadIdx.x;
    if (t >= 1024 * 64) return;
    int c = t >> 6, kp = t & 63;
    unsigned short h0, l0, h1, l1;
    split_limbs(wl4[c * 128 + 2 * kp] * 64.0f, h0, l0);
    split_limbs(wl4[c * 128 + 2 * kp + 1] * 64.0f, h1, l1);
    g_wphi[t] = (u32)h0 | ((u32)h1 << 16);
    g_wplo[t] = (u32)l0 | ((u32)l1 << 16);
}

// ---------------- kernel B: persistent 3-pass split-fp16 mma, direct-fragment smem ----------------
#define WS2 68                       // W plane stride (u32): banks 4*gid4+tig all distinct
#define HS2 136                      // H plane stride (u32): banks 8*tig+gid4 all distinct
#define KB_W_U (2 * 128 * WS2)       // 17408 u32
#define KB_H_U (2 * 64 * HS2)        // 17408 u32 per tile buffer
#define KB_SMEM_BYTES ((KB_W_U + 2 * KB_H_U) * 4)   // 208896 B

__global__ __launch_bounds__(256, 1)
void kB(const float* __restrict__ bl4) {
    extern __shared__ float smf[];
    u32* swp = reinterpret_cast<u32*>(smf);          // hi plane [128][WS2], lo at +128*WS2
    u32* hbuf0 = swp + KB_W_U;
    u32* hbuf1 = hbuf0 + KB_H_U;
    __shared__ unsigned char gid_s[128];

    const int tid = threadIdx.x;
    const int bid = blockIdx.x;
    const int b  = bid >> 6;
    const int pg = (bid >> 3) & 7;
    const int cc = bid & 7;
    const int c0 = cc * 128;

    // W tile: both planes, [r][kp] with stride WS2
#pragma unroll
    for (int j = 0; j < 8; j++) {
        int idx = j * 256 + tid;                     // 2048 uint4 total
        int r = idx >> 4, q = (idx & 15) * 4;
        uint4 vh = *reinterpret_cast<const uint4*>(g_wphi + (size_t)(c0 + r) * 64 + q);
        uint4 vl = *reinterpret_cast<const uint4*>(g_wplo + (size_t)(c0 + r) * 64 + q);
        *reinterpret_cast<uint4*>(&swp[r * WS2 + q]) = vh;
        *reinterpret_cast<uint4*>(&swp[128 * WS2 + r * WS2 + q]) = vl;
    }

    const u32 hadd[2] = { smem_u32(hbuf0), smem_u32(hbuf1) };
    // prefetch H tile 0 (hi rows 0..63, lo rows 64..127)
    {
        const int pbase = pg * 2048;
#pragma unroll
        for (int j = 0; j < 16; j++) {
            int idx = j * 256 + tid;                 // 4096 uint4
            int row = idx >> 5, q = (idx & 31) * 4;
            const u32* src = (row < 64)
                ? g_hhi + ((size_t)b * 64 + row) * NPTS + pbase + q
                : g_hlo + ((size_t)b * 64 + (row - 64)) * NPTS + pbase + q;
            CP_ASYNC16(hadd[0] + (u32)(row * HS2 + q) * 4, src);
        }
        CP_COMMIT();
    }

    const int lane = tid & 31, wrp = tid >> 5;
    const int mw = wrp >> 1;
    const int nw = wrp & 1;
    const int gid4 = lane >> 2, tig = lane & 3;
    const int cw = mw * 32, pw = nw * 64;

#pragma unroll 1
    for (int t = 0; t < 16; t++) {
        const int pbase = (pg * 16 + t) * 128;
        u32* shp = (t & 1) ? hbuf1 : hbuf0;
        if (t + 1 < 16) {
            const int pn = (pg * 16 + t + 1) * 128;
            const u32 dsta = hadd[(t + 1) & 1];
#pragma unroll
            for (int j = 0; j < 16; j++) {
                int idx = j * 256 + tid;
                int row = idx >> 5, q = (idx & 31) * 4;
                const u32* src = (row < 64)
                    ? g_hhi + ((size_t)b * 64 + row) * NPTS + pn + q
                    : g_hlo + ((size_t)b * 64 + (row - 64)) * NPTS + pn + q;
                CP_ASYNC16(dsta + (u32)(row * HS2 + q) * 4, src);
            }
            CP_COMMIT();
            CP_WAIT1();
        } else {
            CP_WAIT0();
        }
        if (tid < 128) gid_s[tid] = g_gid[b * NPTS + pbase + tid];
        __syncthreads();

        float acc[2][8][4];
#pragma unroll
        for (int mt = 0; mt < 2; mt++)
#pragma unroll
            for (int nt = 0; nt < 8; nt++)
#pragma unroll
                for (int j = 0; j < 4; j++) acc[mt][nt][j] = 0.0f;

        const u32* swhi = swp;
        const u32* swlo = swp + 128 * WS2;
        const u32* shhi = shp;
        const u32* shlo = shp + 64 * HS2;

#pragma unroll 1
        for (int kk = 0; kk < 8; kk++) {
            const int kpb = kk * 8;
            u32 ahi[2][4], alo[2][4];
#pragma unroll
            for (int mt = 0; mt < 2; mt++) {
                const int r0 = cw + mt * 16 + gid4;
#pragma unroll
                for (int q = 0; q < 4; q++) {
                    const int rr = r0 + (q & 1) * 8;
                    const int kq = kpb + tig + (q >> 1) * 4;
                    ahi[mt][q] = swhi[rr * WS2 + kq];
                    alo[mt][q] = swlo[rr * WS2 + kq];
                }
            }
            u32 bhi[8][2], blo[8][2];
#pragma unroll
            for (int nt = 0; nt < 8; nt++) {
                const int pp = pw + nt * 8 + gid4;
#pragma unroll
                for (int q = 0; q < 2; q++) {
                    const int kr = kpb + tig + q * 4;
                    bhi[nt][q] = shhi[kr * HS2 + pp];
                    blo[nt][q] = shlo[kr * HS2 + pp];
                }
            }
#pragma unroll
            for (int mt = 0; mt < 2; mt++)
#pragma unroll
                for (int nt = 0; nt < 8; nt++) {
                    mma16(acc[mt][nt], ahi[mt], bhi[nt]);
                    mma16(acc[mt][nt], ahi[mt], blo[nt]);
                    mma16(acc[mt][nt], alo[mt], bhi[nt]);
                }
        }
        __syncthreads();   // all reads of shp done; reuse region for staging

        u64* skey = reinterpret_cast<u64*>(shp);             // 8 KB
        float* sg = reinterpret_cast<float*>(skey + 1024);   // 16 KB
        const int slot = nw * 4 + tig;
#pragma unroll
        for (int mt = 0; mt < 2; mt++)
#pragma unroll
            for (int hf = 0; hf < 2; hf++) {
                const int c = cw + mt * 16 + gid4 + hf * 8;
                const float bias_c = __ldg(&bl4[c0 + c]);
                u64 key = 0ull;
                float g0 = 0.f, g1 = 0.f, g2 = 0.f, g3 = 0.f;
#pragma unroll
                for (int nt = 0; nt < 8; nt++)
#pragma unroll
                    for (int jj = 0; jj < 2; jj++) {
                        float val = fmaxf(fmaf(acc[mt][nt][hf * 2 + jj], 0.015625f, bias_c), 0.0f);
                        const int pl = pw + nt * 8 + tig * 2 + jj;
                        u64 k = ((u64)__float_as_uint(val) << 32) |
                                (u64)(0xFFFFFFFFu - (u32)(pbase + pl));
                        if (k > key) key = k;
                        const int gi = gid_s[pl];
                        g0 = fmaxf(g0, gi == 0 ? val : 0.f);
                        g1 = fmaxf(g1, gi == 1 ? val : 0.f);
                        g2 = fmaxf(g2, gi == 2 ? val : 0.f);
                        g3 = fmaxf(g3, gi == 3 ? val : 0.f);
                    }
                skey[c * 8 + slot] = key;
                sg[(c * 8 + slot) * 4 + 0] = g0;
                sg[(c * 8 + slot) * 4 + 1] = g1;
                sg[(c * 8 + slot) * 4 + 2] = g2;
                sg[(c * 8 + slot) * 4 + 3] = g3;
            }
        __syncthreads();

        if (tid < 128) {
            const int c = tid;
            u64 m = skey[c * 8];
            float mg[4] = { sg[c * 32 + 0], sg[c * 32 + 1], sg[c * 32 + 2], sg[c * 32 + 3] };
#pragma unroll
            for (int q = 1; q < 8; q++) {
                u64 e = skey[c * 8 + q];
                if (e > m) m = e;
#pragma unroll
                for (int g = 0; g < 4; g++) mg[g] = fmaxf(mg[g], sg[(c * 8 + q) * 4 + g]);
            }
            atomicMax(&g_pmax[b * 1024 + c0 + c], m);
#pragma unroll
            for (int g = 0; g < 4; g++)
                atomicMax(&g_gmax[g * 1024 + c0 + c], __float_as_uint(mg[g]));
        }
        __syncthreads();   // staging reads done before buffer is prefetch-overwritten
    }
}

// ---------------- init + tail MLPs (unchanged) ----------------
__global__ void kInit() {
    int t = blockIdx.x * blockDim.x + threadIdx.x;
    if (t < BATCH * 1024) g_pmax[t] = 0ull;
    if (t < 4 * 1024) g_gmax[t] = 0u;
}

__global__ void kC1(const float* __restrict__ wg0, const float* __restrict__ bg0,
                    const float* __restrict__ wgr0, const float* __restrict__ bgr0,
                    float* __restrict__ out) {
    const int gtid = blockIdx.x * blockDim.x + threadIdx.x;
    if (gtid < BATCH * 1024) {
        unsigned long long pv = g_pmax[gtid];
        out[4096 + gtid] = (float)(0xFFFFFFFFu - (unsigned int)(pv & 0xFFFFFFFFull));
    }
    const int wid = gtid >> 5;
    const int lane = gtid & 31;
    const int row = wid >> 9;
    const int j = wid & 511;
    if (row > 16) return;
    float s = 0.0f;
    if (row < 16) {
        const float* wr = wg0 + (size_t)j * 1024;
        const unsigned long long* pbuf = g_pmax + row * 1024;
        for (int k = lane; k < 1024; k += 32)
            s = fmaf(wr[k], __uint_as_float((unsigned int)(pbuf[k] >> 32)), s);
    } else {
        const float* wr = wgr0 + (size_t)j * 4096;
        for (int k = lane; k < 4096; k += 32)
            s = fmaf(wr[k], __uint_as_float(g_gmax[k]), s);
    }
#pragma unroll
    for (int o = 16; o; o >>= 1) s += __shfl_xor_sync(0xFFFFFFFFu, s, o);
    if (lane == 0) {
        float bb = (row < 16) ? bg0[j] : bgr0[j];
        g_u1[row * 512 + j] = fmaxf(s + bb, 0.0f);
    }
}

__global__ void kC2(const float* __restrict__ wg1, const float* __restrict__ bg1,
                    const float* __restrict__ wgr1, const float* __restrict__ bgr1,
                    float* __restrict__ out) {
    const int gtid = blockIdx.x * blockDim.x + threadIdx.x;
    const int wid = gtid >> 5;
    const int lane = gtid & 31;
    const int row = wid >> 7;
    const int j = wid & 127;
    if (row > 16) return;
    const float* wr = ((row < 16) ? wg1 : wgr1) + (size_t)j * 512;
    const float* in = g_u1 + row * 512;
    float s = 0.0f;
    for (int k = lane; k < 512; k += 32) s = fmaf(wr[k], in[k], s);
#pragma unroll
    for (int o = 16; o; o >>= 1) s += __shfl_xor_sync(0xFFFFFFFFu, s, o);
    s = __shfl_sync(0xFFFFFFFFu, s, 0);
    float bb = (row < 16) ? bg1[j] : bgr1[j];
    float val = fmaxf(s + bb, 0.0f);
    if (row < 16) {
        if (lane == 0) out[row * 256 + 128 + j] = val;
    } else {
        if (lane < 16) out[lane * 256 + j] = val;
    }
}

// ---------------- launch ----------------
extern "C" void kernel_launch(void* const* d_in, const int* in_sizes, int n_in,
                              void* d_out, int out_size) {
    const float* points = (const float*)d_in[0];
    const float* wl0 = (const float*)d_in[1];  const float* bl0 = (const float*)d_in[2];
    const float* wl1 = (const float*)d_in[3];  const float* bl1 = (const float*)d_in[4];
    const float* wl2 = (const float*)d_in[5];  const float* bl2 = (const float*)d_in[6];
    const float* wl3 = (const float*)d_in[7];  const float* bl3 = (const float*)d_in[8];
    const float* wl4 = (const float*)d_in[9];  const float* bl4 = (const float*)d_in[10];
    const float* wg0 = (const float*)d_in[11]; const float* bg0 = (const float*)d_in[12];
    const float* wg1 = (const float*)d_in[13]; const float* bg1 = (const float*)d_in[14];
    const float* wgr0 = (const float*)d_in[15]; const float* bgr0 = (const float*)d_in[16];
    const float* wgr1 = (const float*)d_in[17]; const float* bgr1 = (const float*)d_in[18];
    float* out = (float*)d_out;

    cudaFuncSetAttribute(kA, cudaFuncAttributeMaxDynamicSharedMemorySize,
                         KA_SMEM_FLOATS * (int)sizeof(float));
    cudaFuncSetAttribute(kB, cudaFuncAttributeMaxDynamicSharedMemorySize, KB_SMEM_BYTES);

    kInit<<<64, 256>>>();
    kW<<<256, 256>>>(wl4);
    kA<<<(BATCH * NPTS) / 128, 128, KA_SMEM_FLOATS * sizeof(float)>>>(
        points, wl0, bl0, wl1, bl1, wl2, bl2, wl3, bl3);
    kB<<<1024, 256, KB_SMEM_BYTES>>>(bl4);
    kC1<<<1088, 256>>>(wg0, bg0, wgr0, bgr0, out);
    kC2<<<272, 256>>>(wg1, bg1, wgr1, bgr1, out);
}